// round 10
// baseline (speedup 1.0000x reference)
#include <cuda_runtime.h>
#include <cuda_bf16.h>
#include <cstdint>

// LSTM T=128, B=128, I=H=1024.  mma.sync bf16 split-precision (3-term).
// R10 = R8 (best: 3040us) with ONE change: flag-array grid barrier
//       (per-CTA release stores + acquire polling) instead of atomic counter.

constexpr int T_STEPS = 128, BATCH = 128, HDIM = 1024, KDIM = 1024;
constexpr int TB = T_STEPS * BATCH;   // 16384
constexpr int NG = 4 * HDIM;          // 4096
constexpr int NCTA = 128;

// ---------------- scratch ----------------------------------------------------
__device__ __nv_bfloat16 g_Xhi[(size_t)TB * KDIM];
__device__ __nv_bfloat16 g_Xlo[(size_t)TB * KDIM];
__device__ __nv_bfloat16 g_WxThi[(size_t)NG * KDIM];
__device__ __nv_bfloat16 g_WxTlo[(size_t)NG * KDIM];
__device__ __nv_bfloat16 g_WhThi[(size_t)NG * KDIM];
__device__ __nv_bfloat16 g_WhTlo[(size_t)NG * KDIM];
__device__ float g_bias[NG];
__device__ float g_xw[(size_t)TB * NG];              // 256 MB
__device__ __nv_bfloat16 g_hhi[2][BATCH * HDIM];
__device__ __nv_bfloat16 g_hlo[2][BATCH * HDIM];
__device__ unsigned g_flags[NCTA];

// ---------------- helpers ----------------------------------------------------
static __device__ __forceinline__ uint32_t smem_u32(const void* p) {
    uint32_t a;
    asm("{ .reg .u64 t; cvta.to.shared.u64 t, %1; cvt.u32.u64 %0, t; }" : "=r"(a) : "l"(p));
    return a;
}
static __device__ __forceinline__ void ldsm4(uint32_t addr, uint32_t& r0, uint32_t& r1,
                                             uint32_t& r2, uint32_t& r3) {
    asm volatile("ldmatrix.sync.aligned.m8n8.x4.shared.b16 {%0,%1,%2,%3}, [%4];"
                 : "=r"(r0), "=r"(r1), "=r"(r2), "=r"(r3) : "r"(addr));
}
static __device__ __forceinline__ void mma16816(float* d, const uint32_t* a,
                                                uint32_t b0, uint32_t b1) {
    asm volatile(
        "mma.sync.aligned.m16n8k16.row.col.f32.bf16.bf16.f32 "
        "{%0,%1,%2,%3},{%4,%5,%6,%7},{%8,%9},{%0,%1,%2,%3};"
        : "+f"(d[0]), "+f"(d[1]), "+f"(d[2]), "+f"(d[3])
        : "r"(a[0]), "r"(a[1]), "r"(a[2]), "r"(a[3]), "r"(b0), "r"(b1));
}
#define CPA(dst, src) asm volatile("cp.async.cg.shared.global [%0], [%1], 16;" :: "r"(dst), "l"(src))
#define CPC() asm volatile("cp.async.commit_group;" ::: "memory")
#define CPW0() asm volatile("cp.async.wait_group 0;" ::: "memory")
#define CPW1() asm volatile("cp.async.wait_group 1;" ::: "memory")

static __device__ __forceinline__ float sigmoidf_(float x) {
    return __fdividef(1.0f, 1.0f + __expf(-x));
}
static __device__ __forceinline__ float tanh_fast(float x) {
    float a = fabsf(x);
    float z = __expf(-2.0f * a);
    float t = __fdividef(1.0f - z, 1.0f + z);
    return copysignf(t, x);
}

// ---------------- Phase 0 -----------------------------------------------------
__global__ void splitx_kernel(const float* __restrict__ X) {
    size_t i = ((size_t)blockIdx.x * 256 + threadIdx.x) * 4;
    float4 v = *(const float4*)(X + i);
    __nv_bfloat16 h0 = __float2bfloat16(v.x), h1 = __float2bfloat16(v.y);
    __nv_bfloat16 h2 = __float2bfloat16(v.z), h3 = __float2bfloat16(v.w);
    __nv_bfloat16 l0 = __float2bfloat16(v.x - __bfloat162float(h0));
    __nv_bfloat16 l1 = __float2bfloat16(v.y - __bfloat162float(h1));
    __nv_bfloat16 l2 = __float2bfloat16(v.z - __bfloat162float(h2));
    __nv_bfloat16 l3 = __float2bfloat16(v.w - __bfloat162float(h3));
    ((__nv_bfloat162*)(g_Xhi + i))[0] = __nv_bfloat162(h0, h1);
    ((__nv_bfloat162*)(g_Xhi + i))[1] = __nv_bfloat162(h2, h3);
    ((__nv_bfloat162*)(g_Xlo + i))[0] = __nv_bfloat162(l0, l1);
    ((__nv_bfloat162*)(g_Xlo + i))[1] = __nv_bfloat162(l2, l3);
}

__global__ void splitw_kernel(const float* __restrict__ W0, const float* __restrict__ W1,
                              const float* __restrict__ W2, const float* __restrict__ W3,
                              __nv_bfloat16* __restrict__ hiT, __nv_bfloat16* __restrict__ loT) {
    __shared__ float sm[32][33];
    const int g = blockIdx.z;
    const float* W = (g == 0) ? W0 : (g == 1) ? W1 : (g == 2) ? W2 : W3;
    const int k0 = blockIdx.x * 32, u0 = blockIdx.y * 32;
    const int tx = threadIdx.x & 31, ty = threadIdx.x >> 5;
    #pragma unroll
    for (int i = 0; i < 4; i++)
        sm[ty + 8 * i][tx] = W[(size_t)(k0 + ty + 8 * i) * HDIM + u0 + tx];
    __syncthreads();
    #pragma unroll
    for (int i = 0; i < 4; i++) {
        int ul = ty + 8 * i;
        float v = sm[tx][ul];
        __nv_bfloat16 h = __float2bfloat16(v);
        __nv_bfloat16 l = __float2bfloat16(v - __bfloat162float(h));
        size_t n = (size_t)(u0 + ul) * 4 + g;
        hiT[n * KDIM + k0 + tx] = h;
        loT[n * KDIM + k0 + tx] = l;
    }
}

__global__ void bias_kernel(const float* __restrict__ bf, const float* __restrict__ bi,
                            const float* __restrict__ bc, const float* __restrict__ bo) {
    int u = blockIdx.x * 256 + threadIdx.x;
    g_bias[u * 4 + 0] = bf[u];
    g_bias[u * 4 + 1] = bi[u];
    g_bias[u * 4 + 2] = bc[u];
    g_bias[u * 4 + 3] = bo[u];
    if (u < NCTA) g_flags[u] = 0;
}

// ---------------- Phase 1: GEMM1 (R8/R5 version: 2-stage, 2 CTAs/SM) ----------
constexpr int G1_SA = 40;                               // elems
constexpr int G1_MAT = 128 * G1_SA * 2;                 // 10240 B per matrix
constexpr int G1_STAGE = 4 * G1_MAT;                    // 40960 B
constexpr int G1_SMEM = 2 * G1_STAGE;                   // 81920

__global__ __launch_bounds__(256)
void gemm1_kernel() {
    extern __shared__ char smem[];
    const uint32_t sb = smem_u32(smem);
    const int tid = threadIdx.x, wid = tid >> 5, l = tid & 31;
    const int wm = wid & 3, wn = wid >> 2;
    const int n0 = blockIdx.x * 128, m0 = blockIdx.y * 128;

    const int lr = tid >> 2, lc = tid & 3;
    auto issue = [&](int kc, int s) {
        uint32_t base = sb + s * G1_STAGE;
        #pragma unroll
        for (int i = 0; i < 2; i++) {
            int row = lr + 64 * i;
            uint32_t off = (uint32_t)(row * G1_SA + lc * 8) * 2;
            size_t ga = (size_t)(m0 + row) * KDIM + kc * 32 + lc * 8;
            size_t gb = (size_t)(n0 + row) * KDIM + kc * 32 + lc * 8;
            CPA(base + 0 * G1_MAT + off, g_Xhi + ga);
            CPA(base + 1 * G1_MAT + off, g_Xlo + ga);
            CPA(base + 2 * G1_MAT + off, g_WxThi + gb);
            CPA(base + 3 * G1_MAT + off, g_WxTlo + gb);
        }
        CPC();
    };

    uint32_t aoff[2];
    #pragma unroll
    for (int mb = 0; mb < 2; mb++)
        aoff[mb] = ((wm * 32 + mb * 16 + (l & 15)) * G1_SA + (l >> 4) * 8) * 2;
    uint32_t boff[4];
    #pragma unroll
    for (int nbp = 0; nbp < 4; nbp++)
        boff[nbp] = ((wn * 64 + nbp * 16 + (l & 7) + (l >> 4) * 8) * G1_SA +
                     ((l >> 3) & 1) * 8) * 2;

    float acc[2][4][2][4];
    #pragma unroll
    for (int a = 0; a < 2; a++)
        #pragma unroll
        for (int b = 0; b < 4; b++)
            #pragma unroll
            for (int c = 0; c < 2; c++)
                #pragma unroll
                for (int d = 0; d < 4; d++) acc[a][b][c][d] = 0.f;

    issue(0, 0);
    issue(1, 1);
    for (int kc = 0; kc < 32; kc++) {
        if (kc == 31) { CPW0(); } else { CPW1(); }
        __syncthreads();
        const uint32_t base = sb + (kc & 1) * G1_STAGE;
        #pragma unroll
        for (int kk = 0; kk < 2; kk++) {
            uint32_t ah[2][4], al[2][4];
            #pragma unroll
            for (int mb = 0; mb < 2; mb++) {
                ldsm4(base + 0 * G1_MAT + aoff[mb] + kk * 32, ah[mb][0], ah[mb][1], ah[mb][2], ah[mb][3]);
                ldsm4(base + 1 * G1_MAT + aoff[mb] + kk * 32, al[mb][0], al[mb][1], al[mb][2], al[mb][3]);
            }
            #pragma unroll
            for (int nbp = 0; nbp < 4; nbp++) {
                uint32_t bh0, bh1, bh2, bh3, bl0, bl1, bl2, bl3;
                ldsm4(base + 2 * G1_MAT + boff[nbp] + kk * 32, bh0, bh1, bh2, bh3);
                ldsm4(base + 3 * G1_MAT + boff[nbp] + kk * 32, bl0, bl1, bl2, bl3);
                #pragma unroll
                for (int mb = 0; mb < 2; mb++) {
                    mma16816(acc[mb][nbp][0], ah[mb], bh0, bh1);
                    mma16816(acc[mb][nbp][0], al[mb], bh0, bh1);
                    mma16816(acc[mb][nbp][0], ah[mb], bl0, bl1);
                    mma16816(acc[mb][nbp][1], ah[mb], bh2, bh3);
                    mma16816(acc[mb][nbp][1], al[mb], bh2, bh3);
                    mma16816(acc[mb][nbp][1], ah[mb], bl2, bl3);
                }
            }
        }
        __syncthreads();
        if (kc + 2 < 32) issue(kc + 2, kc & 1);
    }

    #pragma unroll
    for (int mb = 0; mb < 2; mb++) {
        #pragma unroll
        for (int nbp = 0; nbp < 4; nbp++) {
            #pragma unroll
            for (int nb = 0; nb < 2; nb++) {
                int n = n0 + wn * 64 + nbp * 16 + nb * 8 + (l & 3) * 2;
                float2 bz = *(const float2*)(g_bias + n);
                int m = m0 + wm * 32 + mb * 16 + (l >> 2);
                float* p0 = g_xw + (size_t)m * NG + n;
                float* p1 = g_xw + (size_t)(m + 8) * NG + n;
                *(float2*)p0 = make_float2(acc[mb][nbp][nb][0] + bz.x, acc[mb][nbp][nb][1] + bz.y);
                *(float2*)p1 = make_float2(acc[mb][nbp][nb][2] + bz.x, acc[mb][nbp][nb][3] + bz.y);
            }
        }
    }
}

// ---------------- Phase 2: persistent recurrence (R8) -------------------------
// Swizzled A stages: tile row = 128 B (64 bf16), chunk16 index c' = c ^ (row&7).
constexpr int P_HALF = 128 * 128;                   // 16384 B (one of hi/lo)
constexpr int P_STAGE = 2 * P_HALF;                 // 32768 B
constexpr int P_NSTG = 3;
constexpr int P_SB = 1032;                          // elems (1024 + 8 pad)
constexpr int P_B_HI = P_NSTG * P_STAGE;            // 98304
constexpr int P_B_LO = P_B_HI + 32 * P_SB * 2;      // 164352
constexpr int P_SMEM = P_B_LO + 32 * P_SB * 2;      // 230400
constexpr int PRE_S = 36;

__global__ __launch_bounds__(256)
void lstm_persistent_kernel(float* __restrict__ out, int tail_mode) {
    extern __shared__ char smem[];
    const uint32_t sb = smem_u32(smem);
    const int tid = threadIdx.x, wid = tid >> 5, l = tid & 31;
    const int wm = wid & 3, wn = wid >> 2;
    const int n0 = blockIdx.x * 32;

    // resident B (Wh slice hi+lo), padded stride (2064 B/row -> conflict-free)
    {
        const __nv_bfloat16* srcH = g_WhThi + (size_t)n0 * KDIM;
        const __nv_bfloat16* srcL = g_WhTlo + (size_t)n0 * KDIM;
        for (int idx = tid; idx < 32 * 128; idx += 256) {
            int row = idx >> 7, c16 = idx & 127;
            uint32_t off = (uint32_t)(row * P_SB + c16 * 8) * 2;
            CPA(sb + P_B_HI + off, srcH + (size_t)row * KDIM + c16 * 8);
            CPA(sb + P_B_LO + off, srcL + (size_t)row * KDIM + c16 * 8);
        }
        CPC(); CPW0();
    }
    __syncthreads();

    // A ldmatrix addressing (swizzled)
    uint32_t arowb[2], arxor[2];
    #pragma unroll
    for (int mb = 0; mb < 2; mb++) {
        int row = wm * 32 + mb * 16 + (l & 15);
        arowb[mb] = (uint32_t)row * 128;
        arxor[mb] = (uint32_t)(row & 7);
    }
    const uint32_t achalf = (uint32_t)(l >> 4);
    const uint32_t boff = ((wn * 16 + (l & 7) + (l >> 4) * 8) * P_SB + ((l >> 3) & 1) * 8) * 2;

    const int ar = tid >> 3, ac = tid & 7;
    float* pre = (float*)smem;
    const int u0 = n0 >> 2;
    int cm[4], cul[4];
    #pragma unroll
    for (int i = 0; i < 4; i++) { int cell = tid + 256 * i; cm[i] = cell >> 3; cul[i] = cell & 7; }
    float creg[4] = {0.f, 0.f, 0.f, 0.f};

    for (int t = 0; t < T_STEPS; t++) {
        float4 gx[4];
        #pragma unroll
        for (int i = 0; i < 4; i++)
            gx[i] = *(const float4*)(g_xw + ((size_t)t * BATCH + cm[i]) * NG + n0 + cul[i] * 4);

        float acc[2][2][4];
        #pragma unroll
        for (int a = 0; a < 2; a++)
            #pragma unroll
            for (int b = 0; b < 2; b++)
                #pragma unroll
                for (int d = 0; d < 4; d++) acc[a][b][d] = 0.f;

        if (t > 0) {
            const __nv_bfloat16* Ahi = g_hhi[t & 1];
            const __nv_bfloat16* Alo = g_hlo[t & 1];
            auto issue = [&](int kc) {
                uint32_t base = sb + (kc % P_NSTG) * P_STAGE;
                #pragma unroll
                for (int i = 0; i < 4; i++) {
                    int row = ar + 32 * i;
                    uint32_t off = (uint32_t)row * 128 + (uint32_t)((ac ^ (row & 7)) * 16);
                    size_t ga = (size_t)row * KDIM + kc * 64 + ac * 8;
                    CPA(base + off, Ahi + ga);
                    CPA(base + P_HALF + off, Alo + ga);
                }
                CPC();
            };
            issue(0);
            issue(1);
            for (int kc = 0; kc < 16; kc++) {
                if (kc == 15) { CPW0(); } else { CPW1(); }
                __syncthreads();
                if (kc + 2 < 16) issue(kc + 2); else CPC();
                const uint32_t base = sb + (kc % P_NSTG) * P_STAGE;
                #pragma unroll
                for (int kk = 0; kk < 4; kk++) {
                    uint32_t ah[2][4], al[2][4];
                    #pragma unroll
                    for (int mb = 0; mb < 2; mb++) {
                        uint32_t c = 2 * kk + achalf;
                        uint32_t aoff = arowb[mb] + ((c ^ arxor[mb]) << 4);
                        ldsm4(base + aoff, ah[mb][0], ah[mb][1], ah[mb][2], ah[mb][3]);
                        ldsm4(base + P_HALF + aoff, al[mb][0], al[mb][1], al[mb][2], al[mb][3]);
                    }
                    const uint32_t kb = (uint32_t)(kc * 128 + kk * 32);
                    uint32_t bh0, bh1, bh2, bh3, bl0, bl1, bl2, bl3;
                    ldsm4(sb + P_B_HI + boff + kb, bh0, bh1, bh2, bh3);
                    ldsm4(sb + P_B_LO + boff + kb, bl0, bl1, bl2, bl3);
                    #pragma unroll
                    for (int mb = 0; mb < 2; mb++) {
                        mma16816(acc[mb][0], ah[mb], bh0, bh1);
                        mma16816(acc[mb][0], al[mb], bh0, bh1);
                        mma16816(acc[mb][0], ah[mb], bl0, bl1);
                        mma16816(acc[mb][1], ah[mb], bh2, bh3);
                        mma16816(acc[mb][1], al[mb], bh2, bh3);
                        mma16816(acc[mb][1], ah[mb], bl2, bl3);
                    }
                }
            }
            __syncthreads();   // protect A-stage region before pre-dump reuse
        }

        // dump preactivations to smem (A stage region is free now)
        #pragma unroll
        for (int mb = 0; mb < 2; mb++) {
            #pragma unroll
            for (int nb = 0; nb < 2; nb++) {
                int row = wm * 32 + mb * 16 + (l >> 2);
                int col = wn * 16 + nb * 8 + (l & 3) * 2;
                *(float2*)(pre + row * PRE_S + col) = make_float2(acc[mb][nb][0], acc[mb][nb][1]);
                *(float2*)(pre + (row + 8) * PRE_S + col) = make_float2(acc[mb][nb][2], acc[mb][nb][3]);
            }
        }
        __syncthreads();

        const int wbuf = (t + 1) & 1;
        #pragma unroll
        for (int i = 0; i < 4; i++) {
            const int m = cm[i], ul = cul[i];
            float4 pa = *(const float4*)(pre + m * PRE_S + ul * 4);
            float pf = pa.x + gx[i].x, pi = pa.y + gx[i].y;
            float pc = pa.z + gx[i].z, po = pa.w + gx[i].w;
            float fg = sigmoidf_(pf);
            float ig = sigmoidf_(pi);
            float ct = tanh_fast(pc);
            float og = sigmoidf_(po);
            float cn = fg * creg[i] + ig * ct;
            float hn = og * tanh_fast(cn);
            creg[i] = cn;
            const int u = u0 + ul;
            const int cu = m * HDIM + u;
            out[((size_t)t * BATCH + m) * HDIM + u] = hn;
            __nv_bfloat16 hh = __float2bfloat16(hn);
            __nv_bfloat16 hl = __float2bfloat16(hn - __bfloat162float(hh));
            g_hhi[wbuf][cu] = hh;
            g_hlo[wbuf][cu] = hl;
            if (t == T_STEPS - 1 && tail_mode > 0) {
                size_t TBH = (size_t)T_STEPS * BATCH * HDIM;
                out[TBH + cu] = hn;
                if (tail_mode > 1) out[TBH + (size_t)BATCH * HDIM + cu] = cn;
            }
        }

        // ---- flag-array grid barrier (no single-address atomic contention) ----
        __syncthreads();
        if (t < T_STEPS - 1) {
            if (tid == 0) {
                __threadfence();
                asm volatile("st.global.relaxed.gpu.u32 [%0], %1;"
                             :: "l"(g_flags + blockIdx.x), "r"((unsigned)(t + 1)) : "memory");
            }
            if (tid < NCTA) {
                unsigned v;
                do {
                    asm volatile("ld.global.acquire.gpu.u32 %0, [%1];"
                                 : "=r"(v) : "l"(g_flags + tid));
                } while (v < (unsigned)(t + 1));
            }
            __syncthreads();
        }
    }
}

// ---------------- launch ------------------------------------------------------
extern "C" void kernel_launch(void* const* d_in, const int* in_sizes, int n_in,
                              void* d_out, int out_size)
{
    const float* X   = (const float*)d_in[0];
    const float* Wxf = (const float*)d_in[1];
    const float* Whf = (const float*)d_in[2];
    const float* bf  = (const float*)d_in[3];
    const float* Wxi = (const float*)d_in[4];
    const float* Whi = (const float*)d_in[5];
    const float* bi  = (const float*)d_in[6];
    const float* Wxc = (const float*)d_in[7];
    const float* Whc = (const float*)d_in[8];
    const float* bc  = (const float*)d_in[9];
    const float* Wxo = (const float*)d_in[10];
    const float* Who = (const float*)d_in[11];
    const float* bo  = (const float*)d_in[12];
    float* out = (float*)d_out;

    __nv_bfloat16 *wxhi, *wxlo, *whhi, *whlo;
    cudaGetSymbolAddress((void**)&wxhi, g_WxThi);
    cudaGetSymbolAddress((void**)&wxlo, g_WxTlo);
    cudaGetSymbolAddress((void**)&whhi, g_WhThi);
    cudaGetSymbolAddress((void**)&whlo, g_WhTlo);

    cudaFuncSetAttribute(gemm1_kernel, cudaFuncAttributeMaxDynamicSharedMemorySize, G1_SMEM);
    cudaFuncSetAttribute(lstm_persistent_kernel, cudaFuncAttributeMaxDynamicSharedMemorySize, P_SMEM);

    splitx_kernel<<<(TB * KDIM) / 1024, 256>>>(X);
    splitw_kernel<<<dim3(32, 32, 4), 256>>>(Wxf, Wxi, Wxc, Wxo, wxhi, wxlo);
    splitw_kernel<<<dim3(32, 32, 4), 256>>>(Whf, Whi, Whc, Who, whhi, whlo);
    bias_kernel<<<4, 256>>>(bf, bi, bc, bo);  // also zeroes g_flags

    gemm1_kernel<<<dim3(NG / 128, TB / 128), 256, G1_SMEM>>>();

    long long TBH  = (long long)T_STEPS * BATCH * HDIM;
    long long tail = (long long)out_size - TBH;
    int tail_mode = (tail >= 2LL * BATCH * HDIM) ? 2 : (tail >= (long long)BATCH * HDIM) ? 1 : 0;

    lstm_persistent_kernel<<<NCTA, 256, P_SMEM>>>(out, tail_mode);
}

// round 11
// speedup vs baseline: 1.2986x; 1.2986x over previous
#include <cuda_runtime.h>
#include <cuda_fp16.h>
#include <cstdint>

// LSTM T=128, B=128, I=H=1024.  mma.sync fp16 split-precision.
// R11 = R8 structure exactly, with fp16 storage. gemm1: 3-term (err ~2^-22).
//       Recurrence: 2-term (Ah*Bh + Al*Bh; Wh-lo dropped, err ~2^-12 on W)
//       -> 33% fewer HMMAs per step.

constexpr int T_STEPS = 128, BATCH = 128, HDIM = 1024, KDIM = 1024;
constexpr int TB = T_STEPS * BATCH;   // 16384
constexpr int NG = 4 * HDIM;          // 4096
constexpr int NCTA = 128;

// ---------------- scratch ----------------------------------------------------
__device__ __half g_Xhi[(size_t)TB * KDIM];
__device__ __half g_Xlo[(size_t)TB * KDIM];
__device__ __half g_WxThi[(size_t)NG * KDIM];
__device__ __half g_WxTlo[(size_t)NG * KDIM];
__device__ __half g_WhThi[(size_t)NG * KDIM];
__device__ float g_bias[NG];
__device__ float g_xw[(size_t)TB * NG];              // 256 MB
__device__ __half g_hhi[2][BATCH * HDIM];
__device__ __half g_hlo[2][BATCH * HDIM];
__device__ unsigned g_bar;

// ---------------- helpers ----------------------------------------------------
static __device__ __forceinline__ uint32_t smem_u32(const void* p) {
    uint32_t a;
    asm("{ .reg .u64 t; cvta.to.shared.u64 t, %1; cvt.u32.u64 %0, t; }" : "=r"(a) : "l"(p));
    return a;
}
static __device__ __forceinline__ void ldsm4(uint32_t addr, uint32_t& r0, uint32_t& r1,
                                             uint32_t& r2, uint32_t& r3) {
    asm volatile("ldmatrix.sync.aligned.m8n8.x4.shared.b16 {%0,%1,%2,%3}, [%4];"
                 : "=r"(r0), "=r"(r1), "=r"(r2), "=r"(r3) : "r"(addr));
}
static __device__ __forceinline__ void mma16816(float* d, const uint32_t* a,
                                                uint32_t b0, uint32_t b1) {
    asm volatile(
        "mma.sync.aligned.m16n8k16.row.col.f32.f16.f16.f32 "
        "{%0,%1,%2,%3},{%4,%5,%6,%7},{%8,%9},{%0,%1,%2,%3};"
        : "+f"(d[0]), "+f"(d[1]), "+f"(d[2]), "+f"(d[3])
        : "r"(a[0]), "r"(a[1]), "r"(a[2]), "r"(a[3]), "r"(b0), "r"(b1));
}
#define CPA(dst, src) asm volatile("cp.async.cg.shared.global [%0], [%1], 16;" :: "r"(dst), "l"(src))
#define CPC() asm volatile("cp.async.commit_group;" ::: "memory")
#define CPW0() asm volatile("cp.async.wait_group 0;" ::: "memory")
#define CPW1() asm volatile("cp.async.wait_group 1;" ::: "memory")

static __device__ __forceinline__ float sigmoidf_(float x) {
    return __fdividef(1.0f, 1.0f + __expf(-x));
}
static __device__ __forceinline__ float tanh_fast(float x) {
    float a = fabsf(x);
    float z = __expf(-2.0f * a);
    float t = __fdividef(1.0f - z, 1.0f + z);
    return copysignf(t, x);
}

// ---------------- Phase 0 -----------------------------------------------------
__global__ void splitx_kernel(const float* __restrict__ X) {
    size_t i = ((size_t)blockIdx.x * 256 + threadIdx.x) * 4;
    float4 v = *(const float4*)(X + i);
    __half h0 = __float2half(v.x), h1 = __float2half(v.y);
    __half h2 = __float2half(v.z), h3 = __float2half(v.w);
    __half l0 = __float2half(v.x - __half2float(h0));
    __half l1 = __float2half(v.y - __half2float(h1));
    __half l2 = __float2half(v.z - __half2float(h2));
    __half l3 = __float2half(v.w - __half2float(h3));
    ((__half2*)(g_Xhi + i))[0] = __half2(h0, h1);
    ((__half2*)(g_Xhi + i))[1] = __half2(h2, h3);
    ((__half2*)(g_Xlo + i))[0] = __half2(l0, l1);
    ((__half2*)(g_Xlo + i))[1] = __half2(l2, l3);
}

// transpose + split; loT may be null (hi-only, used for Wh)
__global__ void splitw_kernel(const float* __restrict__ W0, const float* __restrict__ W1,
                              const float* __restrict__ W2, const float* __restrict__ W3,
                              __half* __restrict__ hiT, __half* __restrict__ loT) {
    __shared__ float sm[32][33];
    const int g = blockIdx.z;
    const float* W = (g == 0) ? W0 : (g == 1) ? W1 : (g == 2) ? W2 : W3;
    const int k0 = blockIdx.x * 32, u0 = blockIdx.y * 32;
    const int tx = threadIdx.x & 31, ty = threadIdx.x >> 5;
    #pragma unroll
    for (int i = 0; i < 4; i++)
        sm[ty + 8 * i][tx] = W[(size_t)(k0 + ty + 8 * i) * HDIM + u0 + tx];
    __syncthreads();
    #pragma unroll
    for (int i = 0; i < 4; i++) {
        int ul = ty + 8 * i;
        float v = sm[tx][ul];
        __half h = __float2half(v);
        size_t n = (size_t)(u0 + ul) * 4 + g;
        hiT[n * KDIM + k0 + tx] = h;
        if (loT) loT[n * KDIM + k0 + tx] = __float2half(v - __half2float(h));
    }
}

__global__ void bias_kernel(const float* __restrict__ bf, const float* __restrict__ bi,
                            const float* __restrict__ bc, const float* __restrict__ bo) {
    int u = blockIdx.x * 256 + threadIdx.x;
    g_bias[u * 4 + 0] = bf[u];
    g_bias[u * 4 + 1] = bi[u];
    g_bias[u * 4 + 2] = bc[u];
    g_bias[u * 4 + 3] = bo[u];
    if (u == 0) g_bar = 0;
}

// ---------------- Phase 1: GEMM1 (R8/R5: 2-stage, 3-term) ---------------------
constexpr int G1_SA = 40;                               // elems
constexpr int G1_MAT = 128 * G1_SA * 2;                 // 10240 B per matrix
constexpr int G1_STAGE = 4 * G1_MAT;                    // 40960 B
constexpr int G1_SMEM = 2 * G1_STAGE;                   // 81920

__global__ __launch_bounds__(256)
void gemm1_kernel() {
    extern __shared__ char smem[];
    const uint32_t sb = smem_u32(smem);
    const int tid = threadIdx.x, wid = tid >> 5, l = tid & 31;
    const int wm = wid & 3, wn = wid >> 2;
    const int n0 = blockIdx.x * 128, m0 = blockIdx.y * 128;

    const int lr = tid >> 2, lc = tid & 3;
    auto issue = [&](int kc, int s) {
        uint32_t base = sb + s * G1_STAGE;
        #pragma unroll
        for (int i = 0; i < 2; i++) {
            int row = lr + 64 * i;
            uint32_t off = (uint32_t)(row * G1_SA + lc * 8) * 2;
            size_t ga = (size_t)(m0 + row) * KDIM + kc * 32 + lc * 8;
            size_t gb = (size_t)(n0 + row) * KDIM + kc * 32 + lc * 8;
            CPA(base + 0 * G1_MAT + off, g_Xhi + ga);
            CPA(base + 1 * G1_MAT + off, g_Xlo + ga);
            CPA(base + 2 * G1_MAT + off, g_WxThi + gb);
            CPA(base + 3 * G1_MAT + off, g_WxTlo + gb);
        }
        CPC();
    };

    uint32_t aoff[2];
    #pragma unroll
    for (int mb = 0; mb < 2; mb++)
        aoff[mb] = ((wm * 32 + mb * 16 + (l & 15)) * G1_SA + (l >> 4) * 8) * 2;
    uint32_t boff[4];
    #pragma unroll
    for (int nbp = 0; nbp < 4; nbp++)
        boff[nbp] = ((wn * 64 + nbp * 16 + (l & 7) + (l >> 4) * 8) * G1_SA +
                     ((l >> 3) & 1) * 8) * 2;

    float acc[2][4][2][4];
    #pragma unroll
    for (int a = 0; a < 2; a++)
        #pragma unroll
        for (int b = 0; b < 4; b++)
            #pragma unroll
            for (int c = 0; c < 2; c++)
                #pragma unroll
                for (int d = 0; d < 4; d++) acc[a][b][c][d] = 0.f;

    issue(0, 0);
    issue(1, 1);
    for (int kc = 0; kc < 32; kc++) {
        if (kc == 31) { CPW0(); } else { CPW1(); }
        __syncthreads();
        const uint32_t base = sb + (kc & 1) * G1_STAGE;
        #pragma unroll
        for (int kk = 0; kk < 2; kk++) {
            uint32_t ah[2][4], al[2][4];
            #pragma unroll
            for (int mb = 0; mb < 2; mb++) {
                ldsm4(base + 0 * G1_MAT + aoff[mb] + kk * 32, ah[mb][0], ah[mb][1], ah[mb][2], ah[mb][3]);
                ldsm4(base + 1 * G1_MAT + aoff[mb] + kk * 32, al[mb][0], al[mb][1], al[mb][2], al[mb][3]);
            }
            #pragma unroll
            for (int nbp = 0; nbp < 4; nbp++) {
                uint32_t bh0, bh1, bh2, bh3, bl0, bl1, bl2, bl3;
                ldsm4(base + 2 * G1_MAT + boff[nbp] + kk * 32, bh0, bh1, bh2, bh3);
                ldsm4(base + 3 * G1_MAT + boff[nbp] + kk * 32, bl0, bl1, bl2, bl3);
                #pragma unroll
                for (int mb = 0; mb < 2; mb++) {
                    mma16816(acc[mb][nbp][0], ah[mb], bh0, bh1);
                    mma16816(acc[mb][nbp][0], al[mb], bh0, bh1);
                    mma16816(acc[mb][nbp][0], ah[mb], bl0, bl1);
                    mma16816(acc[mb][nbp][1], ah[mb], bh2, bh3);
                    mma16816(acc[mb][nbp][1], al[mb], bh2, bh3);
                    mma16816(acc[mb][nbp][1], ah[mb], bl2, bl3);
                }
            }
        }
        __syncthreads();
        if (kc + 2 < 32) issue(kc + 2, kc & 1);
    }

    #pragma unroll
    for (int mb = 0; mb < 2; mb++) {
        #pragma unroll
        for (int nbp = 0; nbp < 4; nbp++) {
            #pragma unroll
            for (int nb = 0; nb < 2; nb++) {
                int n = n0 + wn * 64 + nbp * 16 + nb * 8 + (l & 3) * 2;
                float2 bz = *(const float2*)(g_bias + n);
                int m = m0 + wm * 32 + mb * 16 + (l >> 2);
                float* p0 = g_xw + (size_t)m * NG + n;
                float* p1 = g_xw + (size_t)(m + 8) * NG + n;
                *(float2*)p0 = make_float2(acc[mb][nbp][nb][0] + bz.x, acc[mb][nbp][nb][1] + bz.y);
                *(float2*)p1 = make_float2(acc[mb][nbp][nb][2] + bz.x, acc[mb][nbp][nb][3] + bz.y);
            }
        }
    }
}

// ---------------- Phase 2: persistent recurrence (2-term, B-hi only) ----------
// Swizzled A stages: tile row = 128 B (64 fp16), chunk16 index c' = c ^ (row&7).
constexpr int P_HALF = 128 * 128;                   // 16384 B (one of hi/lo)
constexpr int P_STAGE = 2 * P_HALF;                 // 32768 B
constexpr int P_NSTG = 3;
constexpr int P_SB = 1032;                          // elems (1024 + 8 pad)
constexpr int P_B_HI = P_NSTG * P_STAGE;            // 98304
constexpr int P_SMEM = P_B_HI + 32 * P_SB * 2;      // 164352
constexpr int PRE_S = 36;

__global__ __launch_bounds__(256)
void lstm_persistent_kernel(float* __restrict__ out, int tail_mode) {
    extern __shared__ char smem[];
    const uint32_t sb = smem_u32(smem);
    const int tid = threadIdx.x, wid = tid >> 5, l = tid & 31;
    const int wm = wid & 3, wn = wid >> 2;
    const int n0 = blockIdx.x * 32;

    // resident B (Wh slice, hi only)
    {
        const __half* srcH = g_WhThi + (size_t)n0 * KDIM;
        for (int idx = tid; idx < 32 * 128; idx += 256) {
            int row = idx >> 7, c16 = idx & 127;
            uint32_t off = (uint32_t)(row * P_SB + c16 * 8) * 2;
            CPA(sb + P_B_HI + off, srcH + (size_t)row * KDIM + c16 * 8);
        }
        CPC(); CPW0();
    }
    __syncthreads();

    // A ldmatrix addressing (swizzled)
    uint32_t arowb[2], arxor[2];
    #pragma unroll
    for (int mb = 0; mb < 2; mb++) {
        int row = wm * 32 + mb * 16 + (l & 15);
        arowb[mb] = (uint32_t)row * 128;
        arxor[mb] = (uint32_t)(row & 7);
    }
    const uint32_t achalf = (uint32_t)(l >> 4);
    const uint32_t boff = ((wn * 16 + (l & 7) + (l >> 4) * 8) * P_SB + ((l >> 3) & 1) * 8) * 2;

    const int ar = tid >> 3, ac = tid & 7;
    float* pre = (float*)smem;
    const int u0 = n0 >> 2;
    int cm[4], cul[4];
    #pragma unroll
    for (int i = 0; i < 4; i++) { int cell = tid + 256 * i; cm[i] = cell >> 3; cul[i] = cell & 7; }
    float creg[4] = {0.f, 0.f, 0.f, 0.f};

    for (int t = 0; t < T_STEPS; t++) {
        float4 gx[4];
        #pragma unroll
        for (int i = 0; i < 4; i++)
            gx[i] = *(const float4*)(g_xw + ((size_t)t * BATCH + cm[i]) * NG + n0 + cul[i] * 4);

        float acc[2][2][4];
        #pragma unroll
        for (int a = 0; a < 2; a++)
            #pragma unroll
            for (int b = 0; b < 2; b++)
                #pragma unroll
                for (int d = 0; d < 4; d++) acc[a][b][d] = 0.f;

        if (t > 0) {
            const __half* Ahi = g_hhi[t & 1];
            const __half* Alo = g_hlo[t & 1];
            auto issue = [&](int kc) {
                uint32_t base = sb + (kc % P_NSTG) * P_STAGE;
                #pragma unroll
                for (int i = 0; i < 4; i++) {
                    int row = ar + 32 * i;
                    uint32_t off = (uint32_t)row * 128 + (uint32_t)((ac ^ (row & 7)) * 16);
                    size_t ga = (size_t)row * KDIM + kc * 64 + ac * 8;
                    CPA(base + off, Ahi + ga);
                    CPA(base + P_HALF + off, Alo + ga);
                }
                CPC();
            };
            issue(0);
            issue(1);
            for (int kc = 0; kc < 16; kc++) {
                if (kc == 15) { CPW0(); } else { CPW1(); }
                __syncthreads();
                if (kc + 2 < 16) issue(kc + 2); else CPC();
                const uint32_t base = sb + (kc % P_NSTG) * P_STAGE;
                #pragma unroll
                for (int kk = 0; kk < 4; kk++) {
                    uint32_t ah[2][4], al[2][4];
                    #pragma unroll
                    for (int mb = 0; mb < 2; mb++) {
                        uint32_t c = 2 * kk + achalf;
                        uint32_t aoff = arowb[mb] + ((c ^ arxor[mb]) << 4);
                        ldsm4(base + aoff, ah[mb][0], ah[mb][1], ah[mb][2], ah[mb][3]);
                        ldsm4(base + P_HALF + aoff, al[mb][0], al[mb][1], al[mb][2], al[mb][3]);
                    }
                    const uint32_t kb = (uint32_t)(kc * 128 + kk * 32);
                    uint32_t bh0, bh1, bh2, bh3;
                    ldsm4(sb + P_B_HI + boff + kb, bh0, bh1, bh2, bh3);
                    #pragma unroll
                    for (int mb = 0; mb < 2; mb++) {
                        mma16816(acc[mb][0], ah[mb], bh0, bh1);
                        mma16816(acc[mb][0], al[mb], bh0, bh1);
                        mma16816(acc[mb][1], ah[mb], bh2, bh3);
                        mma16816(acc[mb][1], al[mb], bh2, bh3);
                    }
                }
            }
            __syncthreads();   // protect A-stage region before pre-dump reuse
        }

        // dump preactivations to smem (A stage region is free now)
        #pragma unroll
        for (int mb = 0; mb < 2; mb++) {
            #pragma unroll
            for (int nb = 0; nb < 2; nb++) {
                int row = wm * 32 + mb * 16 + (l >> 2);
                int col = wn * 16 + nb * 8 + (l & 3) * 2;
                *(float2*)(pre + row * PRE_S + col) = make_float2(acc[mb][nb][0], acc[mb][nb][1]);
                *(float2*)(pre + (row + 8) * PRE_S + col) = make_float2(acc[mb][nb][2], acc[mb][nb][3]);
            }
        }
        __syncthreads();

        const int wbuf = (t + 1) & 1;
        #pragma unroll
        for (int i = 0; i < 4; i++) {
            const int m = cm[i], ul = cul[i];
            float4 pa = *(const float4*)(pre + m * PRE_S + ul * 4);
            float pf = pa.x + gx[i].x, pi = pa.y + gx[i].y;
            float pc = pa.z + gx[i].z, po = pa.w + gx[i].w;
            float fg = sigmoidf_(pf);
            float ig = sigmoidf_(pi);
            float ct = tanh_fast(pc);
            float og = sigmoidf_(po);
            float cn = fg * creg[i] + ig * ct;
            float hn = og * tanh_fast(cn);
            creg[i] = cn;
            const int u = u0 + ul;
            const int cu = m * HDIM + u;
            out[((size_t)t * BATCH + m) * HDIM + u] = hn;
            __half hh = __float2half(hn);
            __half hl = __float2half(hn - __half2float(hh));
            g_hhi[wbuf][cu] = hh;
            g_hlo[wbuf][cu] = hl;
            if (t == T_STEPS - 1 && tail_mode > 0) {
                size_t TBH = (size_t)T_STEPS * BATCH * HDIM;
                out[TBH + cu] = hn;
                if (tail_mode > 1) out[TBH + (size_t)BATCH * HDIM + cu] = cn;
            }
        }

        // ---- grid barrier (R8: atomic counter + single-thread acquire poll) ----
        __syncthreads();
        if (t < T_STEPS - 1) {
            if (tid == 0) {
                __threadfence();
                atomicAdd(&g_bar, 1u);
                const unsigned target = (unsigned)NCTA * (unsigned)(t + 1);
                unsigned v;
                do {
                    asm volatile("ld.global.acquire.gpu.u32 %0, [%1];"
                                 : "=r"(v) : "l"(&g_bar));
                } while (v < target);
            }
            __syncthreads();
        }
    }
}

// ---------------- launch ------------------------------------------------------
extern "C" void kernel_launch(void* const* d_in, const int* in_sizes, int n_in,
                              void* d_out, int out_size)
{
    const float* X   = (const float*)d_in[0];
    const float* Wxf = (const float*)d_in[1];
    const float* Whf = (const float*)d_in[2];
    const float* bf  = (const float*)d_in[3];
    const float* Wxi = (const float*)d_in[4];
    const float* Whi = (const float*)d_in[5];
    const float* bi  = (const float*)d_in[6];
    const float* Wxc = (const float*)d_in[7];
    const float* Whc = (const float*)d_in[8];
    const float* bc  = (const float*)d_in[9];
    const float* Wxo = (const float*)d_in[10];
    const float* Who = (const float*)d_in[11];
    const float* bo  = (const float*)d_in[12];
    float* out = (float*)d_out;

    __half *wxhi, *wxlo, *whhi;
    cudaGetSymbolAddress((void**)&wxhi, g_WxThi);
    cudaGetSymbolAddress((void**)&wxlo, g_WxTlo);
    cudaGetSymbolAddress((void**)&whhi, g_WhThi);

    cudaFuncSetAttribute(gemm1_kernel, cudaFuncAttributeMaxDynamicSharedMemorySize, G1_SMEM);
    cudaFuncSetAttribute(lstm_persistent_kernel, cudaFuncAttributeMaxDynamicSharedMemorySize, P_SMEM);

    splitx_kernel<<<(TB * KDIM) / 1024, 256>>>(X);
    splitw_kernel<<<dim3(32, 32, 4), 256>>>(Wxf, Wxi, Wxc, Wxo, wxhi, wxlo);
    splitw_kernel<<<dim3(32, 32, 4), 256>>>(Whf, Whi, Whc, Who, whhi, (__half*)nullptr);
    bias_kernel<<<4, 256>>>(bf, bi, bc, bo);  // also zeroes g_bar

    gemm1_kernel<<<dim3(NG / 128, TB / 128), 256, G1_SMEM>>>();

    long long TBH  = (long long)T_STEPS * BATCH * HDIM;
    long long tail = (long long)out_size - TBH;
    int tail_mode = (tail >= 2LL * BATCH * HDIM) ? 2 : (tail >= (long long)BATCH * HDIM) ? 1 : 0;

    lstm_persistent_kernel<<<NCTA, 256, P_SMEM>>>(out, tail_mode);
}

// round 12
// speedup vs baseline: 1.6678x; 1.2843x over previous
#include <cuda_runtime.h>
#include <cuda_fp16.h>
#include <cstdint>

// LSTM T=128, B=128, I=H=1024.  mma.sync fp16.
// R12 = R11 with pure-fp16 recurrence (1-term: Ah*Bh; h-lo dropped).
//       gemm1 stays 3-term fp16 split.

constexpr int T_STEPS = 128, BATCH = 128, HDIM = 1024, KDIM = 1024;
constexpr int TB = T_STEPS * BATCH;   // 16384
constexpr int NG = 4 * HDIM;          // 4096
constexpr int NCTA = 128;

// ---------------- scratch ----------------------------------------------------
__device__ __half g_Xhi[(size_t)TB * KDIM];
__device__ __half g_Xlo[(size_t)TB * KDIM];
__device__ __half g_WxThi[(size_t)NG * KDIM];
__device__ __half g_WxTlo[(size_t)NG * KDIM];
__device__ __half g_WhThi[(size_t)NG * KDIM];
__device__ float g_bias[NG];
__device__ float g_xw[(size_t)TB * NG];              // 256 MB
__device__ __half g_h[2][BATCH * HDIM];
__device__ unsigned g_bar;

// ---------------- helpers ----------------------------------------------------
static __device__ __forceinline__ uint32_t smem_u32(const void* p) {
    uint32_t a;
    asm("{ .reg .u64 t; cvta.to.shared.u64 t, %1; cvt.u32.u64 %0, t; }" : "=r"(a) : "l"(p));
    return a;
}
static __device__ __forceinline__ void ldsm4(uint32_t addr, uint32_t& r0, uint32_t& r1,
                                             uint32_t& r2, uint32_t& r3) {
    asm volatile("ldmatrix.sync.aligned.m8n8.x4.shared.b16 {%0,%1,%2,%3}, [%4];"
                 : "=r"(r0), "=r"(r1), "=r"(r2), "=r"(r3) : "r"(addr));
}
static __device__ __forceinline__ void mma16816(float* d, const uint32_t* a,
                                                uint32_t b0, uint32_t b1) {
    asm volatile(
        "mma.sync.aligned.m16n8k16.row.col.f32.f16.f16.f32 "
        "{%0,%1,%2,%3},{%4,%5,%6,%7},{%8,%9},{%0,%1,%2,%3};"
        : "+f"(d[0]), "+f"(d[1]), "+f"(d[2]), "+f"(d[3])
        : "r"(a[0]), "r"(a[1]), "r"(a[2]), "r"(a[3]), "r"(b0), "r"(b1));
}
#define CPA(dst, src) asm volatile("cp.async.cg.shared.global [%0], [%1], 16;" :: "r"(dst), "l"(src))
#define CPC() asm volatile("cp.async.commit_group;" ::: "memory")
#define CPW0() asm volatile("cp.async.wait_group 0;" ::: "memory")
#define CPW1() asm volatile("cp.async.wait_group 1;" ::: "memory")

static __device__ __forceinline__ float sigmoidf_(float x) {
    return __fdividef(1.0f, 1.0f + __expf(-x));
}
static __device__ __forceinline__ float tanh_fast(float x) {
    float a = fabsf(x);
    float z = __expf(-2.0f * a);
    float t = __fdividef(1.0f - z, 1.0f + z);
    return copysignf(t, x);
}

// ---------------- Phase 0 -----------------------------------------------------
__global__ void splitx_kernel(const float* __restrict__ X) {
    size_t i = ((size_t)blockIdx.x * 256 + threadIdx.x) * 4;
    float4 v = *(const float4*)(X + i);
    __half h0 = __float2half(v.x), h1 = __float2half(v.y);
    __half h2 = __float2half(v.z), h3 = __float2half(v.w);
    __half l0 = __float2half(v.x - __half2float(h0));
    __half l1 = __float2half(v.y - __half2float(h1));
    __half l2 = __float2half(v.z - __half2float(h2));
    __half l3 = __float2half(v.w - __half2float(h3));
    ((__half2*)(g_Xhi + i))[0] = __half2(h0, h1);
    ((__half2*)(g_Xhi + i))[1] = __half2(h2, h3);
    ((__half2*)(g_Xlo + i))[0] = __half2(l0, l1);
    ((__half2*)(g_Xlo + i))[1] = __half2(l2, l3);
}

// transpose + split; loT may be null (hi-only, used for Wh)
__global__ void splitw_kernel(const float* __restrict__ W0, const float* __restrict__ W1,
                              const float* __restrict__ W2, const float* __restrict__ W3,
                              __half* __restrict__ hiT, __half* __restrict__ loT) {
    __shared__ float sm[32][33];
    const int g = blockIdx.z;
    const float* W = (g == 0) ? W0 : (g == 1) ? W1 : (g == 2) ? W2 : W3;
    const int k0 = blockIdx.x * 32, u0 = blockIdx.y * 32;
    const int tx = threadIdx.x & 31, ty = threadIdx.x >> 5;
    #pragma unroll
    for (int i = 0; i < 4; i++)
        sm[ty + 8 * i][tx] = W[(size_t)(k0 + ty + 8 * i) * HDIM + u0 + tx];
    __syncthreads();
    #pragma unroll
    for (int i = 0; i < 4; i++) {
        int ul = ty + 8 * i;
        float v = sm[tx][ul];
        __half h = __float2half(v);
        size_t n = (size_t)(u0 + ul) * 4 + g;
        hiT[n * KDIM + k0 + tx] = h;
        if (loT) loT[n * KDIM + k0 + tx] = __float2half(v - __half2float(h));
    }
}

__global__ void bias_kernel(const float* __restrict__ bf, const float* __restrict__ bi,
                            const float* __restrict__ bc, const float* __restrict__ bo) {
    int u = blockIdx.x * 256 + threadIdx.x;
    g_bias[u * 4 + 0] = bf[u];
    g_bias[u * 4 + 1] = bi[u];
    g_bias[u * 4 + 2] = bc[u];
    g_bias[u * 4 + 3] = bo[u];
    if (u == 0) g_bar = 0;
}

// ---------------- Phase 1: GEMM1 (2-stage, 3-term, fp16) ----------------------
constexpr int G1_SA = 40;                               // elems
constexpr int G1_MAT = 128 * G1_SA * 2;                 // 10240 B per matrix
constexpr int G1_STAGE = 4 * G1_MAT;                    // 40960 B
constexpr int G1_SMEM = 2 * G1_STAGE;                   // 81920

__global__ __launch_bounds__(256)
void gemm1_kernel() {
    extern __shared__ char smem[];
    const uint32_t sb = smem_u32(smem);
    const int tid = threadIdx.x, wid = tid >> 5, l = tid & 31;
    const int wm = wid & 3, wn = wid >> 2;
    const int n0 = blockIdx.x * 128, m0 = blockIdx.y * 128;

    const int lr = tid >> 2, lc = tid & 3;
    auto issue = [&](int kc, int s) {
        uint32_t base = sb + s * G1_STAGE;
        #pragma unroll
        for (int i = 0; i < 2; i++) {
            int row = lr + 64 * i;
            uint32_t off = (uint32_t)(row * G1_SA + lc * 8) * 2;
            size_t ga = (size_t)(m0 + row) * KDIM + kc * 32 + lc * 8;
            size_t gb = (size_t)(n0 + row) * KDIM + kc * 32 + lc * 8;
            CPA(base + 0 * G1_MAT + off, g_Xhi + ga);
            CPA(base + 1 * G1_MAT + off, g_Xlo + ga);
            CPA(base + 2 * G1_MAT + off, g_WxThi + gb);
            CPA(base + 3 * G1_MAT + off, g_WxTlo + gb);
        }
        CPC();
    };

    uint32_t aoff[2];
    #pragma unroll
    for (int mb = 0; mb < 2; mb++)
        aoff[mb] = ((wm * 32 + mb * 16 + (l & 15)) * G1_SA + (l >> 4) * 8) * 2;
    uint32_t boff[4];
    #pragma unroll
    for (int nbp = 0; nbp < 4; nbp++)
        boff[nbp] = ((wn * 64 + nbp * 16 + (l & 7) + (l >> 4) * 8) * G1_SA +
                     ((l >> 3) & 1) * 8) * 2;

    float acc[2][4][2][4];
    #pragma unroll
    for (int a = 0; a < 2; a++)
        #pragma unroll
        for (int b = 0; b < 4; b++)
            #pragma unroll
            for (int c = 0; c < 2; c++)
                #pragma unroll
                for (int d = 0; d < 4; d++) acc[a][b][c][d] = 0.f;

    issue(0, 0);
    issue(1, 1);
    for (int kc = 0; kc < 32; kc++) {
        if (kc == 31) { CPW0(); } else { CPW1(); }
        __syncthreads();
        const uint32_t base = sb + (kc & 1) * G1_STAGE;
        #pragma unroll
        for (int kk = 0; kk < 2; kk++) {
            uint32_t ah[2][4], al[2][4];
            #pragma unroll
            for (int mb = 0; mb < 2; mb++) {
                ldsm4(base + 0 * G1_MAT + aoff[mb] + kk * 32, ah[mb][0], ah[mb][1], ah[mb][2], ah[mb][3]);
                ldsm4(base + 1 * G1_MAT + aoff[mb] + kk * 32, al[mb][0], al[mb][1], al[mb][2], al[mb][3]);
            }
            #pragma unroll
            for (int nbp = 0; nbp < 4; nbp++) {
                uint32_t bh0, bh1, bh2, bh3, bl0, bl1, bl2, bl3;
                ldsm4(base + 2 * G1_MAT + boff[nbp] + kk * 32, bh0, bh1, bh2, bh3);
                ldsm4(base + 3 * G1_MAT + boff[nbp] + kk * 32, bl0, bl1, bl2, bl3);
                #pragma unroll
                for (int mb = 0; mb < 2; mb++) {
                    mma16816(acc[mb][nbp][0], ah[mb], bh0, bh1);
                    mma16816(acc[mb][nbp][0], al[mb], bh0, bh1);
                    mma16816(acc[mb][nbp][0], ah[mb], bl0, bl1);
                    mma16816(acc[mb][nbp][1], ah[mb], bh2, bh3);
                    mma16816(acc[mb][nbp][1], al[mb], bh2, bh3);
                    mma16816(acc[mb][nbp][1], ah[mb], bl2, bl3);
                }
            }
        }
        __syncthreads();
        if (kc + 2 < 32) issue(kc + 2, kc & 1);
    }

    #pragma unroll
    for (int mb = 0; mb < 2; mb++) {
        #pragma unroll
        for (int nbp = 0; nbp < 4; nbp++) {
            #pragma unroll
            for (int nb = 0; nb < 2; nb++) {
                int n = n0 + wn * 64 + nbp * 16 + nb * 8 + (l & 3) * 2;
                float2 bz = *(const float2*)(g_bias + n);
                int m = m0 + wm * 32 + mb * 16 + (l >> 2);
                float* p0 = g_xw + (size_t)m * NG + n;
                float* p1 = g_xw + (size_t)(m + 8) * NG + n;
                *(float2*)p0 = make_float2(acc[mb][nbp][nb][0] + bz.x, acc[mb][nbp][nb][1] + bz.y);
                *(float2*)p1 = make_float2(acc[mb][nbp][nb][2] + bz.x, acc[mb][nbp][nb][3] + bz.y);
            }
        }
    }
}

// ---------------- Phase 2: persistent recurrence (pure fp16, 1-term) ----------
// Swizzled A stages: tile row = 128 B (64 fp16), chunk16 index c' = c ^ (row&7).
constexpr int P_STAGE = 128 * 128;                  // 16384 B (hi only)
constexpr int P_NSTG = 3;
constexpr int P_SB = 1032;                          // elems (1024 + 8 pad)
constexpr int P_B_HI = P_NSTG * P_STAGE;            // 49152
constexpr int P_SMEM = P_B_HI + 32 * P_SB * 2;      // 115200
constexpr int PRE_S = 36;

__global__ __launch_bounds__(256)
void lstm_persistent_kernel(float* __restrict__ out, int tail_mode) {
    extern __shared__ char smem[];
    const uint32_t sb = smem_u32(smem);
    const int tid = threadIdx.x, wid = tid >> 5, l = tid & 31;
    const int wm = wid & 3, wn = wid >> 2;
    const int n0 = blockIdx.x * 32;

    // resident B (Wh slice, hi only)
    {
        const __half* srcH = g_WhThi + (size_t)n0 * KDIM;
        for (int idx = tid; idx < 32 * 128; idx += 256) {
            int row = idx >> 7, c16 = idx & 127;
            uint32_t off = (uint32_t)(row * P_SB + c16 * 8) * 2;
            CPA(sb + P_B_HI + off, srcH + (size_t)row * KDIM + c16 * 8);
        }
        CPC(); CPW0();
    }
    __syncthreads();

    // A ldmatrix addressing (swizzled)
    uint32_t arowb[2], arxor[2];
    #pragma unroll
    for (int mb = 0; mb < 2; mb++) {
        int row = wm * 32 + mb * 16 + (l & 15);
        arowb[mb] = (uint32_t)row * 128;
        arxor[mb] = (uint32_t)(row & 7);
    }
    const uint32_t achalf = (uint32_t)(l >> 4);
    const uint32_t boff = ((wn * 16 + (l & 7) + (l >> 4) * 8) * P_SB + ((l >> 3) & 1) * 8) * 2;

    const int ar = tid >> 3, ac = tid & 7;
    float* pre = (float*)smem;
    const int u0 = n0 >> 2;
    int cm[4], cul[4];
    #pragma unroll
    for (int i = 0; i < 4; i++) { int cell = tid + 256 * i; cm[i] = cell >> 3; cul[i] = cell & 7; }
    float creg[4] = {0.f, 0.f, 0.f, 0.f};

    for (int t = 0; t < T_STEPS; t++) {
        float4 gx[4];
        #pragma unroll
        for (int i = 0; i < 4; i++)
            gx[i] = *(const float4*)(g_xw + ((size_t)t * BATCH + cm[i]) * NG + n0 + cul[i] * 4);

        float acc[2][2][4];
        #pragma unroll
        for (int a = 0; a < 2; a++)
            #pragma unroll
            for (int b = 0; b < 2; b++)
                #pragma unroll
                for (int d = 0; d < 4; d++) acc[a][b][d] = 0.f;

        if (t > 0) {
            const __half* Ah = g_h[t & 1];
            auto issue = [&](int kc) {
                uint32_t base = sb + (kc % P_NSTG) * P_STAGE;
                #pragma unroll
                for (int i = 0; i < 4; i++) {
                    int row = ar + 32 * i;
                    uint32_t off = (uint32_t)row * 128 + (uint32_t)((ac ^ (row & 7)) * 16);
                    CPA(base + off, Ah + (size_t)row * KDIM + kc * 64 + ac * 8);
                }
                CPC();
            };
            issue(0);
            issue(1);
            for (int kc = 0; kc < 16; kc++) {
                if (kc == 15) { CPW0(); } else { CPW1(); }
                __syncthreads();
                if (kc + 2 < 16) issue(kc + 2); else CPC();
                const uint32_t base = sb + (kc % P_NSTG) * P_STAGE;
                #pragma unroll
                for (int kk = 0; kk < 4; kk++) {
                    uint32_t ah[2][4];
                    #pragma unroll
                    for (int mb = 0; mb < 2; mb++) {
                        uint32_t c = 2 * kk + achalf;
                        uint32_t aoff = arowb[mb] + ((c ^ arxor[mb]) << 4);
                        ldsm4(base + aoff, ah[mb][0], ah[mb][1], ah[mb][2], ah[mb][3]);
                    }
                    const uint32_t kb = (uint32_t)(kc * 128 + kk * 32);
                    uint32_t bh0, bh1, bh2, bh3;
                    ldsm4(sb + P_B_HI + boff + kb, bh0, bh1, bh2, bh3);
                    #pragma unroll
                    for (int mb = 0; mb < 2; mb++) {
                        mma16816(acc[mb][0], ah[mb], bh0, bh1);
                        mma16816(acc[mb][1], ah[mb], bh2, bh3);
                    }
                }
            }
            __syncthreads();   // protect A-stage region before pre-dump reuse
        }

        // dump preactivations to smem (A stage region is free now)
        #pragma unroll
        for (int mb = 0; mb < 2; mb++) {
            #pragma unroll
            for (int nb = 0; nb < 2; nb++) {
                int row = wm * 32 + mb * 16 + (l >> 2);
                int col = wn * 16 + nb * 8 + (l & 3) * 2;
                *(float2*)(pre + row * PRE_S + col) = make_float2(acc[mb][nb][0], acc[mb][nb][1]);
                *(float2*)(pre + (row + 8) * PRE_S + col) = make_float2(acc[mb][nb][2], acc[mb][nb][3]);
            }
        }
        __syncthreads();

        const int wbuf = (t + 1) & 1;
        #pragma unroll
        for (int i = 0; i < 4; i++) {
            const int m = cm[i], ul = cul[i];
            float4 pa = *(const float4*)(pre + m * PRE_S + ul * 4);
            float pf = pa.x + gx[i].x, pi = pa.y + gx[i].y;
            float pc = pa.z + gx[i].z, po = pa.w + gx[i].w;
            float fg = sigmoidf_(pf);
            float ig = sigmoidf_(pi);
            float ct = tanh_fast(pc);
            float og = sigmoidf_(po);
            float cn = fg * creg[i] + ig * ct;
            float hn = og * tanh_fast(cn);
            creg[i] = cn;
            const int u = u0 + ul;
            const int cu = m * HDIM + u;
            out[((size_t)t * BATCH + m) * HDIM + u] = hn;
            g_h[wbuf][cu] = __float2half(hn);
            if (t == T_STEPS - 1 && tail_mode > 0) {
                size_t TBH = (size_t)T_STEPS * BATCH * HDIM;
                out[TBH + cu] = hn;
                if (tail_mode > 1) out[TBH + (size_t)BATCH * HDIM + cu] = cn;
            }
        }

        // ---- grid barrier (atomic counter + single-thread acquire poll) ----
        __syncthreads();
        if (t < T_STEPS - 1) {
            if (tid == 0) {
                __threadfence();
                atomicAdd(&g_bar, 1u);
                const unsigned target = (unsigned)NCTA * (unsigned)(t + 1);
                unsigned v;
                do {
                    asm volatile("ld.global.acquire.gpu.u32 %0, [%1];"
                                 : "=r"(v) : "l"(&g_bar));
                } while (v < target);
            }
            __syncthreads();
        }
    }
}

// ---------------- launch ------------------------------------------------------
extern "C" void kernel_launch(void* const* d_in, const int* in_sizes, int n_in,
                              void* d_out, int out_size)
{
    const float* X   = (const float*)d_in[0];
    const float* Wxf = (const float*)d_in[1];
    const float* Whf = (const float*)d_in[2];
    const float* bf  = (const float*)d_in[3];
    const float* Wxi = (const float*)d_in[4];
    const float* Whi = (const float*)d_in[5];
    const float* bi  = (const float*)d_in[6];
    const float* Wxc = (const float*)d_in[7];
    const float* Whc = (const float*)d_in[8];
    const float* bc  = (const float*)d_in[9];
    const float* Wxo = (const float*)d_in[10];
    const float* Who = (const float*)d_in[11];
    const float* bo  = (const float*)d_in[12];
    float* out = (float*)d_out;

    __half *wxhi, *wxlo, *whhi;
    cudaGetSymbolAddress((void**)&wxhi, g_WxThi);
    cudaGetSymbolAddress((void**)&wxlo, g_WxTlo);
    cudaGetSymbolAddress((void**)&whhi, g_WhThi);

    cudaFuncSetAttribute(gemm1_kernel, cudaFuncAttributeMaxDynamicSharedMemorySize, G1_SMEM);
    cudaFuncSetAttribute(lstm_persistent_kernel, cudaFuncAttributeMaxDynamicSharedMemorySize, P_SMEM);

    splitx_kernel<<<(TB * KDIM) / 1024, 256>>>(X);
    splitw_kernel<<<dim3(32, 32, 4), 256>>>(Wxf, Wxi, Wxc, Wxo, wxhi, wxlo);
    splitw_kernel<<<dim3(32, 32, 4), 256>>>(Whf, Whi, Whc, Who, whhi, (__half*)nullptr);
    bias_kernel<<<4, 256>>>(bf, bi, bc, bo);  // also zeroes g_bar

    gemm1_kernel<<<dim3(NG / 128, TB / 128), 256, G1_SMEM>>>();

    long long TBH  = (long long)T_STEPS * BATCH * HDIM;
    long long tail = (long long)out_size - TBH;
    int tail_mode = (tail >= 2LL * BATCH * HDIM) ? 2 : (tail >= (long long)BATCH * HDIM) ? 1 : 0;

    lstm_persistent_kernel<<<NCTA, 256, P_SMEM>>>(out, tail_mode);
}

// round 13
// speedup vs baseline: 2.3890x; 1.4324x over previous
#include <cuda_runtime.h>
#include <cuda_fp16.h>
#include <cstdint>

// LSTM T=128, B=128, I=H=1024.  mma.sync fp16.
// R13 = R12 with pure-fp16 gemm1 (1-term: Xh*Wxh). Recurrence unchanged
//       (pure fp16 1-term, persistent, swizzled 3-stage pipeline).

constexpr int T_STEPS = 128, BATCH = 128, HDIM = 1024, KDIM = 1024;
constexpr int TB = T_STEPS * BATCH;   // 16384
constexpr int NG = 4 * HDIM;          // 4096
constexpr int NCTA = 128;

// ---------------- scratch ----------------------------------------------------
__device__ __half g_Xh[(size_t)TB * KDIM];
__device__ __half g_WxTh[(size_t)NG * KDIM];
__device__ __half g_WhTh[(size_t)NG * KDIM];
__device__ float g_bias[NG];
__device__ float g_xw[(size_t)TB * NG];              // 256 MB
__device__ __half g_h[2][BATCH * HDIM];
__device__ unsigned g_bar;

// ---------------- helpers ----------------------------------------------------
static __device__ __forceinline__ uint32_t smem_u32(const void* p) {
    uint32_t a;
    asm("{ .reg .u64 t; cvta.to.shared.u64 t, %1; cvt.u32.u64 %0, t; }" : "=r"(a) : "l"(p));
    return a;
}
static __device__ __forceinline__ void ldsm4(uint32_t addr, uint32_t& r0, uint32_t& r1,
                                             uint32_t& r2, uint32_t& r3) {
    asm volatile("ldmatrix.sync.aligned.m8n8.x4.shared.b16 {%0,%1,%2,%3}, [%4];"
                 : "=r"(r0), "=r"(r1), "=r"(r2), "=r"(r3) : "r"(addr));
}
static __device__ __forceinline__ void mma16816(float* d, const uint32_t* a,
                                                uint32_t b0, uint32_t b1) {
    asm volatile(
        "mma.sync.aligned.m16n8k16.row.col.f32.f16.f16.f32 "
        "{%0,%1,%2,%3},{%4,%5,%6,%7},{%8,%9},{%0,%1,%2,%3};"
        : "+f"(d[0]), "+f"(d[1]), "+f"(d[2]), "+f"(d[3])
        : "r"(a[0]), "r"(a[1]), "r"(a[2]), "r"(a[3]), "r"(b0), "r"(b1));
}
#define CPA(dst, src) asm volatile("cp.async.cg.shared.global [%0], [%1], 16;" :: "r"(dst), "l"(src))
#define CPC() asm volatile("cp.async.commit_group;" ::: "memory")
#define CPW0() asm volatile("cp.async.wait_group 0;" ::: "memory")
#define CPW1() asm volatile("cp.async.wait_group 1;" ::: "memory")

static __device__ __forceinline__ float sigmoidf_(float x) {
    return __fdividef(1.0f, 1.0f + __expf(-x));
}
static __device__ __forceinline__ float tanh_fast(float x) {
    float a = fabsf(x);
    float z = __expf(-2.0f * a);
    float t = __fdividef(1.0f - z, 1.0f + z);
    return copysignf(t, x);
}

// ---------------- Phase 0 -----------------------------------------------------
__global__ void cvtx_kernel(const float* __restrict__ X) {
    size_t i = ((size_t)blockIdx.x * 256 + threadIdx.x) * 4;
    float4 v = *(const float4*)(X + i);
    ((__half2*)(g_Xh + i))[0] = __half2(__float2half(v.x), __float2half(v.y));
    ((__half2*)(g_Xh + i))[1] = __half2(__float2half(v.z), __float2half(v.w));
}

// transpose + convert to fp16 (gate-interleaved [n=u*4+g][k])
__global__ void cvtw_kernel(const float* __restrict__ W0, const float* __restrict__ W1,
                            const float* __restrict__ W2, const float* __restrict__ W3,
                            __half* __restrict__ hiT) {
    __shared__ float sm[32][33];
    const int g = blockIdx.z;
    const float* W = (g == 0) ? W0 : (g == 1) ? W1 : (g == 2) ? W2 : W3;
    const int k0 = blockIdx.x * 32, u0 = blockIdx.y * 32;
    const int tx = threadIdx.x & 31, ty = threadIdx.x >> 5;
    #pragma unroll
    for (int i = 0; i < 4; i++)
        sm[ty + 8 * i][tx] = W[(size_t)(k0 + ty + 8 * i) * HDIM + u0 + tx];
    __syncthreads();
    #pragma unroll
    for (int i = 0; i < 4; i++) {
        int ul = ty + 8 * i;
        size_t n = (size_t)(u0 + ul) * 4 + g;
        hiT[n * KDIM + k0 + tx] = __float2half(sm[tx][ul]);
    }
}

__global__ void bias_kernel(const float* __restrict__ bf, const float* __restrict__ bi,
                            const float* __restrict__ bc, const float* __restrict__ bo) {
    int u = blockIdx.x * 256 + threadIdx.x;
    g_bias[u * 4 + 0] = bf[u];
    g_bias[u * 4 + 1] = bi[u];
    g_bias[u * 4 + 2] = bc[u];
    g_bias[u * 4 + 3] = bo[u];
    if (u == 0) g_bar = 0;
}

// ---------------- Phase 1: GEMM1 (2-stage, pure fp16 1-term) ------------------
constexpr int G1_SA = 40;                               // elems
constexpr int G1_MAT = 128 * G1_SA * 2;                 // 10240 B per matrix
constexpr int G1_STAGE = 2 * G1_MAT;                    // 20480 B (A + B)
constexpr int G1_SMEM = 2 * G1_STAGE;                   // 40960

__global__ __launch_bounds__(256)
void gemm1_kernel() {
    extern __shared__ char smem[];
    const uint32_t sb = smem_u32(smem);
    const int tid = threadIdx.x, wid = tid >> 5, l = tid & 31;
    const int wm = wid & 3, wn = wid >> 2;
    const int n0 = blockIdx.x * 128, m0 = blockIdx.y * 128;

    const int lr = tid >> 2, lc = tid & 3;
    auto issue = [&](int kc, int s) {
        uint32_t base = sb + s * G1_STAGE;
        #pragma unroll
        for (int i = 0; i < 2; i++) {
            int row = lr + 64 * i;
            uint32_t off = (uint32_t)(row * G1_SA + lc * 8) * 2;
            size_t ga = (size_t)(m0 + row) * KDIM + kc * 32 + lc * 8;
            size_t gb = (size_t)(n0 + row) * KDIM + kc * 32 + lc * 8;
            CPA(base + 0 * G1_MAT + off, g_Xh + ga);
            CPA(base + 1 * G1_MAT + off, g_WxTh + gb);
        }
        CPC();
    };

    uint32_t aoff[2];
    #pragma unroll
    for (int mb = 0; mb < 2; mb++)
        aoff[mb] = ((wm * 32 + mb * 16 + (l & 15)) * G1_SA + (l >> 4) * 8) * 2;
    uint32_t boff[4];
    #pragma unroll
    for (int nbp = 0; nbp < 4; nbp++)
        boff[nbp] = ((wn * 64 + nbp * 16 + (l & 7) + (l >> 4) * 8) * G1_SA +
                     ((l >> 3) & 1) * 8) * 2;

    float acc[2][4][2][4];
    #pragma unroll
    for (int a = 0; a < 2; a++)
        #pragma unroll
        for (int b = 0; b < 4; b++)
            #pragma unroll
            for (int c = 0; c < 2; c++)
                #pragma unroll
                for (int d = 0; d < 4; d++) acc[a][b][c][d] = 0.f;

    issue(0, 0);
    issue(1, 1);
    for (int kc = 0; kc < 32; kc++) {
        if (kc == 31) { CPW0(); } else { CPW1(); }
        __syncthreads();
        const uint32_t base = sb + (kc & 1) * G1_STAGE;
        #pragma unroll
        for (int kk = 0; kk < 2; kk++) {
            uint32_t ah[2][4];
            #pragma unroll
            for (int mb = 0; mb < 2; mb++)
                ldsm4(base + 0 * G1_MAT + aoff[mb] + kk * 32, ah[mb][0], ah[mb][1], ah[mb][2], ah[mb][3]);
            #pragma unroll
            for (int nbp = 0; nbp < 4; nbp++) {
                uint32_t bh0, bh1, bh2, bh3;
                ldsm4(base + 1 * G1_MAT + boff[nbp] + kk * 32, bh0, bh1, bh2, bh3);
                #pragma unroll
                for (int mb = 0; mb < 2; mb++) {
                    mma16816(acc[mb][nbp][0], ah[mb], bh0, bh1);
                    mma16816(acc[mb][nbp][1], ah[mb], bh2, bh3);
                }
            }
        }
        __syncthreads();
        if (kc + 2 < 32) issue(kc + 2, kc & 1);
    }

    #pragma unroll
    for (int mb = 0; mb < 2; mb++) {
        #pragma unroll
        for (int nbp = 0; nbp < 4; nbp++) {
            #pragma unroll
            for (int nb = 0; nb < 2; nb++) {
                int n = n0 + wn * 64 + nbp * 16 + nb * 8 + (l & 3) * 2;
                float2 bz = *(const float2*)(g_bias + n);
                int m = m0 + wm * 32 + mb * 16 + (l >> 2);
                float* p0 = g_xw + (size_t)m * NG + n;
                float* p1 = g_xw + (size_t)(m + 8) * NG + n;
                *(float2*)p0 = make_float2(acc[mb][nbp][nb][0] + bz.x, acc[mb][nbp][nb][1] + bz.y);
                *(float2*)p1 = make_float2(acc[mb][nbp][nb][2] + bz.x, acc[mb][nbp][nb][3] + bz.y);
            }
        }
    }
}

// ---------------- Phase 2: persistent recurrence (pure fp16, 1-term) ----------
// Swizzled A stages: tile row = 128 B (64 fp16), chunk16 index c' = c ^ (row&7).
constexpr int P_STAGE = 128 * 128;                  // 16384 B
constexpr int P_NSTG = 3;
constexpr int P_SB = 1032;                          // elems (1024 + 8 pad)
constexpr int P_B_HI = P_NSTG * P_STAGE;            // 49152
constexpr int P_SMEM = P_B_HI + 32 * P_SB * 2;      // 115200
constexpr int PRE_S = 36;

__global__ __launch_bounds__(256)
void lstm_persistent_kernel(float* __restrict__ out, int tail_mode) {
    extern __shared__ char smem[];
    const uint32_t sb = smem_u32(smem);
    const int tid = threadIdx.x, wid = tid >> 5, l = tid & 31;
    const int wm = wid & 3, wn = wid >> 2;
    const int n0 = blockIdx.x * 32;

    // resident B (Wh slice)
    {
        const __half* srcH = g_WhTh + (size_t)n0 * KDIM;
        for (int idx = tid; idx < 32 * 128; idx += 256) {
            int row = idx >> 7, c16 = idx & 127;
            uint32_t off = (uint32_t)(row * P_SB + c16 * 8) * 2;
            CPA(sb + P_B_HI + off, srcH + (size_t)row * KDIM + c16 * 8);
        }
        CPC(); CPW0();
    }
    __syncthreads();

    // A ldmatrix addressing (swizzled)
    uint32_t arowb[2], arxor[2];
    #pragma unroll
    for (int mb = 0; mb < 2; mb++) {
        int row = wm * 32 + mb * 16 + (l & 15);
        arowb[mb] = (uint32_t)row * 128;
        arxor[mb] = (uint32_t)(row & 7);
    }
    const uint32_t achalf = (uint32_t)(l >> 4);
    const uint32_t boff = ((wn * 16 + (l & 7) + (l >> 4) * 8) * P_SB + ((l >> 3) & 1) * 8) * 2;

    const int ar = tid >> 3, ac = tid & 7;
    float* pre = (float*)smem;
    const int u0 = n0 >> 2;
    int cm[4], cul[4];
    #pragma unroll
    for (int i = 0; i < 4; i++) { int cell = tid + 256 * i; cm[i] = cell >> 3; cul[i] = cell & 7; }
    float creg[4] = {0.f, 0.f, 0.f, 0.f};

    for (int t = 0; t < T_STEPS; t++) {
        float4 gx[4];
        #pragma unroll
        for (int i = 0; i < 4; i++)
            gx[i] = *(const float4*)(g_xw + ((size_t)t * BATCH + cm[i]) * NG + n0 + cul[i] * 4);

        float acc[2][2][4];
        #pragma unroll
        for (int a = 0; a < 2; a++)
            #pragma unroll
            for (int b = 0; b < 2; b++)
                #pragma unroll
                for (int d = 0; d < 4; d++) acc[a][b][d] = 0.f;

        if (t > 0) {
            const __half* Ah = g_h[t & 1];
            auto issue = [&](int kc) {
                uint32_t base = sb + (kc % P_NSTG) * P_STAGE;
                #pragma unroll
                for (int i = 0; i < 4; i++) {
                    int row = ar + 32 * i;
                    uint32_t off = (uint32_t)row * 128 + (uint32_t)((ac ^ (row & 7)) * 16);
                    CPA(base + off, Ah + (size_t)row * KDIM + kc * 64 + ac * 8);
                }
                CPC();
            };
            issue(0);
            issue(1);
            for (int kc = 0; kc < 16; kc++) {
                if (kc == 15) { CPW0(); } else { CPW1(); }
                __syncthreads();
                if (kc + 2 < 16) issue(kc + 2); else CPC();
                const uint32_t base = sb + (kc % P_NSTG) * P_STAGE;
                #pragma unroll
                for (int kk = 0; kk < 4; kk++) {
                    uint32_t ah[2][4];
                    #pragma unroll
                    for (int mb = 0; mb < 2; mb++) {
                        uint32_t c = 2 * kk + achalf;
                        uint32_t aoff = arowb[mb] + ((c ^ arxor[mb]) << 4);
                        ldsm4(base + aoff, ah[mb][0], ah[mb][1], ah[mb][2], ah[mb][3]);
                    }
                    const uint32_t kb = (uint32_t)(kc * 128 + kk * 32);
                    uint32_t bh0, bh1, bh2, bh3;
                    ldsm4(sb + P_B_HI + boff + kb, bh0, bh1, bh2, bh3);
                    #pragma unroll
                    for (int mb = 0; mb < 2; mb++) {
                        mma16816(acc[mb][0], ah[mb], bh0, bh1);
                        mma16816(acc[mb][1], ah[mb], bh2, bh3);
                    }
                }
            }
            __syncthreads();   // protect A-stage region before pre-dump reuse
        }

        // dump preactivations to smem (A stage region is free now)
        #pragma unroll
        for (int mb = 0; mb < 2; mb++) {
            #pragma unroll
            for (int nb = 0; nb < 2; nb++) {
                int row = wm * 32 + mb * 16 + (l >> 2);
                int col = wn * 16 + nb * 8 + (l & 3) * 2;
                *(float2*)(pre + row * PRE_S + col) = make_float2(acc[mb][nb][0], acc[mb][nb][1]);
                *(float2*)(pre + (row + 8) * PRE_S + col) = make_float2(acc[mb][nb][2], acc[mb][nb][3]);
            }
        }
        __syncthreads();

        const int wbuf = (t + 1) & 1;
        #pragma unroll
        for (int i = 0; i < 4; i++) {
            const int m = cm[i], ul = cul[i];
            float4 pa = *(const float4*)(pre + m * PRE_S + ul * 4);
            float pf = pa.x + gx[i].x, pi = pa.y + gx[i].y;
            float pc = pa.z + gx[i].z, po = pa.w + gx[i].w;
            float fg = sigmoidf_(pf);
            float ig = sigmoidf_(pi);
            float ct = tanh_fast(pc);
            float og = sigmoidf_(po);
            float cn = fg * creg[i] + ig * ct;
            float hn = og * tanh_fast(cn);
            creg[i] = cn;
            const int u = u0 + ul;
            const int cu = m * HDIM + u;
            out[((size_t)t * BATCH + m) * HDIM + u] = hn;
            g_h[wbuf][cu] = __float2half(hn);
            if (t == T_STEPS - 1 && tail_mode > 0) {
                size_t TBH = (size_t)T_STEPS * BATCH * HDIM;
                out[TBH + cu] = hn;
                if (tail_mode > 1) out[TBH + (size_t)BATCH * HDIM + cu] = cn;
            }
        }

        // ---- grid barrier (atomic counter + single-thread acquire poll) ----
        __syncthreads();
        if (t < T_STEPS - 1) {
            if (tid == 0) {
                __threadfence();
                atomicAdd(&g_bar, 1u);
                const unsigned target = (unsigned)NCTA * (unsigned)(t + 1);
                unsigned v;
                do {
                    asm volatile("ld.global.acquire.gpu.u32 %0, [%1];"
                                 : "=r"(v) : "l"(&g_bar));
                } while (v < target);
            }
            __syncthreads();
        }
    }
}

// ---------------- launch ------------------------------------------------------
extern "C" void kernel_launch(void* const* d_in, const int* in_sizes, int n_in,
                              void* d_out, int out_size)
{
    const float* X   = (const float*)d_in[0];
    const float* Wxf = (const float*)d_in[1];
    const float* Whf = (const float*)d_in[2];
    const float* bf  = (const float*)d_in[3];
    const float* Wxi = (const float*)d_in[4];
    const float* Whi = (const float*)d_in[5];
    const float* bi  = (const float*)d_in[6];
    const float* Wxc = (const float*)d_in[7];
    const float* Whc = (const float*)d_in[8];
    const float* bc  = (const float*)d_in[9];
    const float* Wxo = (const float*)d_in[10];
    const float* Who = (const float*)d_in[11];
    const float* bo  = (const float*)d_in[12];
    float* out = (float*)d_out;

    __half *wxh, *whh;
    cudaGetSymbolAddress((void**)&wxh, g_WxTh);
    cudaGetSymbolAddress((void**)&whh, g_WhTh);

    cudaFuncSetAttribute(gemm1_kernel, cudaFuncAttributeMaxDynamicSharedMemorySize, G1_SMEM);
    cudaFuncSetAttribute(lstm_persistent_kernel, cudaFuncAttributeMaxDynamicSharedMemorySize, P_SMEM);

    cvtx_kernel<<<(TB * KDIM) / 1024, 256>>>(X);
    cvtw_kernel<<<dim3(32, 32, 4), 256>>>(Wxf, Wxi, Wxc, Wxo, wxh);
    cvtw_kernel<<<dim3(32, 32, 4), 256>>>(Whf, Whi, Whc, Who, whh);
    bias_kernel<<<4, 256>>>(bf, bi, bc, bo);  // also zeroes g_bar

    gemm1_kernel<<<dim3(NG / 128, TB / 128), 256, G1_SMEM>>>();

    long long TBH  = (long long)T_STEPS * BATCH * HDIM;
    long long tail = (long long)out_size - TBH;
    int tail_mode = (tail >= 2LL * BATCH * HDIM) ? 2 : (tail >= (long long)BATCH * HDIM) ? 1 : 0;

    lstm_persistent_kernel<<<NCTA, 256, P_SMEM>>>(out, tail_mode);
}

// round 14
// speedup vs baseline: 2.6437x; 1.1066x over previous
#include <cuda_runtime.h>
#include <cuda_fp16.h>
#include <cstdint>

// LSTM T=128, B=128, I=H=1024.  mma.sync fp16 (pure, 1-term both GEMMs).
// R14 = R13 with bigger k-chunks: recurrence 64->128 (8 sync rounds/step),
//       gemm1 32->64 (16 rounds). No arithmetic change.

constexpr int T_STEPS = 128, BATCH = 128, HDIM = 1024, KDIM = 1024;
constexpr int TB = T_STEPS * BATCH;   // 16384
constexpr int NG = 4 * HDIM;          // 4096
constexpr int NCTA = 128;

// ---------------- scratch ----------------------------------------------------
__device__ __half g_Xh[(size_t)TB * KDIM];
__device__ __half g_WxTh[(size_t)NG * KDIM];
__device__ __half g_WhTh[(size_t)NG * KDIM];
__device__ float g_bias[NG];
__device__ float g_xw[(size_t)TB * NG];              // 256 MB
__device__ __half g_h[2][BATCH * HDIM];
__device__ unsigned g_bar;

// ---------------- helpers ----------------------------------------------------
static __device__ __forceinline__ uint32_t smem_u32(const void* p) {
    uint32_t a;
    asm("{ .reg .u64 t; cvta.to.shared.u64 t, %1; cvt.u32.u64 %0, t; }" : "=r"(a) : "l"(p));
    return a;
}
static __device__ __forceinline__ void ldsm4(uint32_t addr, uint32_t& r0, uint32_t& r1,
                                             uint32_t& r2, uint32_t& r3) {
    asm volatile("ldmatrix.sync.aligned.m8n8.x4.shared.b16 {%0,%1,%2,%3}, [%4];"
                 : "=r"(r0), "=r"(r1), "=r"(r2), "=r"(r3) : "r"(addr));
}
static __device__ __forceinline__ void mma16816(float* d, const uint32_t* a,
                                                uint32_t b0, uint32_t b1) {
    asm volatile(
        "mma.sync.aligned.m16n8k16.row.col.f32.f16.f16.f32 "
        "{%0,%1,%2,%3},{%4,%5,%6,%7},{%8,%9},{%0,%1,%2,%3};"
        : "+f"(d[0]), "+f"(d[1]), "+f"(d[2]), "+f"(d[3])
        : "r"(a[0]), "r"(a[1]), "r"(a[2]), "r"(a[3]), "r"(b0), "r"(b1));
}
#define CPA(dst, src) asm volatile("cp.async.cg.shared.global [%0], [%1], 16;" :: "r"(dst), "l"(src))
#define CPC() asm volatile("cp.async.commit_group;" ::: "memory")
#define CPW0() asm volatile("cp.async.wait_group 0;" ::: "memory")
#define CPW1() asm volatile("cp.async.wait_group 1;" ::: "memory")

static __device__ __forceinline__ float sigmoidf_(float x) {
    return __fdividef(1.0f, 1.0f + __expf(-x));
}
static __device__ __forceinline__ float tanh_fast(float x) {
    float a = fabsf(x);
    float z = __expf(-2.0f * a);
    float t = __fdividef(1.0f - z, 1.0f + z);
    return copysignf(t, x);
}

// ---------------- Phase 0 -----------------------------------------------------
__global__ void cvtx_kernel(const float* __restrict__ X) {
    size_t i = ((size_t)blockIdx.x * 256 + threadIdx.x) * 4;
    float4 v = *(const float4*)(X + i);
    ((__half2*)(g_Xh + i))[0] = __half2(__float2half(v.x), __float2half(v.y));
    ((__half2*)(g_Xh + i))[1] = __half2(__float2half(v.z), __float2half(v.w));
}

__global__ void cvtw_kernel(const float* __restrict__ W0, const float* __restrict__ W1,
                            const float* __restrict__ W2, const float* __restrict__ W3,
                            __half* __restrict__ hiT) {
    __shared__ float sm[32][33];
    const int g = blockIdx.z;
    const float* W = (g == 0) ? W0 : (g == 1) ? W1 : (g == 2) ? W2 : W3;
    const int k0 = blockIdx.x * 32, u0 = blockIdx.y * 32;
    const int tx = threadIdx.x & 31, ty = threadIdx.x >> 5;
    #pragma unroll
    for (int i = 0; i < 4; i++)
        sm[ty + 8 * i][tx] = W[(size_t)(k0 + ty + 8 * i) * HDIM + u0 + tx];
    __syncthreads();
    #pragma unroll
    for (int i = 0; i < 4; i++) {
        int ul = ty + 8 * i;
        size_t n = (size_t)(u0 + ul) * 4 + g;
        hiT[n * KDIM + k0 + tx] = __float2half(sm[tx][ul]);
    }
}

__global__ void bias_kernel(const float* __restrict__ bf, const float* __restrict__ bi,
                            const float* __restrict__ bc, const float* __restrict__ bo) {
    int u = blockIdx.x * 256 + threadIdx.x;
    g_bias[u * 4 + 0] = bf[u];
    g_bias[u * 4 + 1] = bi[u];
    g_bias[u * 4 + 2] = bc[u];
    g_bias[u * 4 + 3] = bo[u];
    if (u == 0) g_bar = 0;
}

// ---------------- Phase 1: GEMM1 (2-stage, 64-k chunks, 16 rounds) ------------
constexpr int G1_SA = 72;                               // elems (64 + 8 pad)
constexpr int G1_MAT = 128 * G1_SA * 2;                 // 18432 B per matrix
constexpr int G1_STAGE = 2 * G1_MAT;                    // 36864 B (A + B)
constexpr int G1_SMEM = 2 * G1_STAGE;                   // 73728

__global__ __launch_bounds__(256)
void gemm1_kernel() {
    extern __shared__ char smem[];
    const uint32_t sb = smem_u32(smem);
    const int tid = threadIdx.x, wid = tid >> 5, l = tid & 31;
    const int wm = wid & 3, wn = wid >> 2;
    const int n0 = blockIdx.x * 128, m0 = blockIdx.y * 128;

    const int lr = tid >> 3, lc = tid & 7;   // 32 rows/pass x 8 chunks
    auto issue = [&](int kc, int s) {
        uint32_t base = sb + s * G1_STAGE;
        #pragma unroll
        for (int i = 0; i < 4; i++) {
            int row = lr + 32 * i;
            uint32_t off = (uint32_t)(row * G1_SA + lc * 8) * 2;
            size_t ga = (size_t)(m0 + row) * KDIM + kc * 64 + lc * 8;
            size_t gb = (size_t)(n0 + row) * KDIM + kc * 64 + lc * 8;
            CPA(base + 0 * G1_MAT + off, g_Xh + ga);
            CPA(base + 1 * G1_MAT + off, g_WxTh + gb);
        }
        CPC();
    };

    uint32_t aoff[2];
    #pragma unroll
    for (int mb = 0; mb < 2; mb++)
        aoff[mb] = ((wm * 32 + mb * 16 + (l & 15)) * G1_SA + (l >> 4) * 8) * 2;
    uint32_t boff[4];
    #pragma unroll
    for (int nbp = 0; nbp < 4; nbp++)
        boff[nbp] = ((wn * 64 + nbp * 16 + (l & 7) + (l >> 4) * 8) * G1_SA +
                     ((l >> 3) & 1) * 8) * 2;

    float acc[2][4][2][4];
    #pragma unroll
    for (int a = 0; a < 2; a++)
        #pragma unroll
        for (int b = 0; b < 4; b++)
            #pragma unroll
            for (int c = 0; c < 2; c++)
                #pragma unroll
                for (int d = 0; d < 4; d++) acc[a][b][c][d] = 0.f;

    issue(0, 0);
    issue(1, 1);
    for (int kc = 0; kc < 16; kc++) {
        if (kc == 15) { CPW0(); } else { CPW1(); }
        __syncthreads();
        const uint32_t base = sb + (kc & 1) * G1_STAGE;
        #pragma unroll
        for (int kk = 0; kk < 4; kk++) {
            uint32_t ah[2][4];
            #pragma unroll
            for (int mb = 0; mb < 2; mb++)
                ldsm4(base + 0 * G1_MAT + aoff[mb] + kk * 32, ah[mb][0], ah[mb][1], ah[mb][2], ah[mb][3]);
            #pragma unroll
            for (int nbp = 0; nbp < 4; nbp++) {
                uint32_t bh0, bh1, bh2, bh3;
                ldsm4(base + 1 * G1_MAT + boff[nbp] + kk * 32, bh0, bh1, bh2, bh3);
                #pragma unroll
                for (int mb = 0; mb < 2; mb++) {
                    mma16816(acc[mb][nbp][0], ah[mb], bh0, bh1);
                    mma16816(acc[mb][nbp][1], ah[mb], bh2, bh3);
                }
            }
        }
        __syncthreads();
        if (kc + 2 < 16) issue(kc + 2, kc & 1);
    }

    #pragma unroll
    for (int mb = 0; mb < 2; mb++) {
        #pragma unroll
        for (int nbp = 0; nbp < 4; nbp++) {
            #pragma unroll
            for (int nb = 0; nb < 2; nb++) {
                int n = n0 + wn * 64 + nbp * 16 + nb * 8 + (l & 3) * 2;
                float2 bz = *(const float2*)(g_bias + n);
                int m = m0 + wm * 32 + mb * 16 + (l >> 2);
                float* p0 = g_xw + (size_t)m * NG + n;
                float* p1 = g_xw + (size_t)(m + 8) * NG + n;
                *(float2*)p0 = make_float2(acc[mb][nbp][nb][0] + bz.x, acc[mb][nbp][nb][1] + bz.y);
                *(float2*)p1 = make_float2(acc[mb][nbp][nb][2] + bz.x, acc[mb][nbp][nb][3] + bz.y);
            }
        }
    }
}

// ---------------- Phase 2: persistent recurrence (128-k chunks, 8 rounds) -----
// Swizzled A stages: tile row = 256 B (128 fp16), chunk16 c' = c ^ (row&7).
constexpr int P_STAGE = 128 * 256;                  // 32768 B
constexpr int P_NSTG = 3;
constexpr int P_SB = 1032;                          // elems (1024 + 8 pad)
constexpr int P_B_HI = P_NSTG * P_STAGE;            // 98304
constexpr int P_SMEM = P_B_HI + 32 * P_SB * 2;      // 164352
constexpr int PRE_S = 36;

__global__ __launch_bounds__(256)
void lstm_persistent_kernel(float* __restrict__ out, int tail_mode) {
    extern __shared__ char smem[];
    const uint32_t sb = smem_u32(smem);
    const int tid = threadIdx.x, wid = tid >> 5, l = tid & 31;
    const int wm = wid & 3, wn = wid >> 2;
    const int n0 = blockIdx.x * 32;

    // resident B (Wh slice)
    {
        const __half* srcH = g_WhTh + (size_t)n0 * KDIM;
        for (int idx = tid; idx < 32 * 128; idx += 256) {
            int row = idx >> 7, c16 = idx & 127;
            uint32_t off = (uint32_t)(row * P_SB + c16 * 8) * 2;
            CPA(sb + P_B_HI + off, srcH + (size_t)row * KDIM + c16 * 8);
        }
        CPC(); CPW0();
    }
    __syncthreads();

    // A ldmatrix addressing (swizzled, 256 B rows)
    uint32_t arowb[2], arxor[2];
    #pragma unroll
    for (int mb = 0; mb < 2; mb++) {
        int row = wm * 32 + mb * 16 + (l & 15);
        arowb[mb] = (uint32_t)row * 256;
        arxor[mb] = (uint32_t)(row & 7);
    }
    const uint32_t achalf = (uint32_t)(l >> 4);
    const uint32_t boff = ((wn * 16 + (l & 7) + (l >> 4) * 8) * P_SB + ((l >> 3) & 1) * 8) * 2;

    const int ar = tid >> 4, ac = tid & 15;   // A loader: 16 rows/pass x 16 chunks
    float* pre = (float*)smem;
    const int u0 = n0 >> 2;
    int cm[4], cul[4];
    #pragma unroll
    for (int i = 0; i < 4; i++) { int cell = tid + 256 * i; cm[i] = cell >> 3; cul[i] = cell & 7; }
    float creg[4] = {0.f, 0.f, 0.f, 0.f};

    for (int t = 0; t < T_STEPS; t++) {
        float4 gx[4];
        #pragma unroll
        for (int i = 0; i < 4; i++)
            gx[i] = *(const float4*)(g_xw + ((size_t)t * BATCH + cm[i]) * NG + n0 + cul[i] * 4);

        float acc[2][2][4];
        #pragma unroll
        for (int a = 0; a < 2; a++)
            #pragma unroll
            for (int b = 0; b < 2; b++)
                #pragma unroll
                for (int d = 0; d < 4; d++) acc[a][b][d] = 0.f;

        if (t > 0) {
            const __half* Ah = g_h[t & 1];
            auto issue = [&](int kc) {
                uint32_t base = sb + (kc % P_NSTG) * P_STAGE;
                #pragma unroll
                for (int i = 0; i < 8; i++) {
                    int row = ar + 16 * i;
                    uint32_t off = (uint32_t)row * 256 + (uint32_t)((ac ^ (row & 7)) * 16);
                    CPA(base + off, Ah + (size_t)row * KDIM + kc * 128 + ac * 8);
                }
                CPC();
            };
            issue(0);
            issue(1);
            for (int kc = 0; kc < 8; kc++) {
                if (kc == 7) { CPW0(); } else { CPW1(); }
                __syncthreads();
                if (kc + 2 < 8) issue(kc + 2); else CPC();
                const uint32_t base = sb + (kc % P_NSTG) * P_STAGE;
                #pragma unroll
                for (int kk = 0; kk < 8; kk++) {
                    uint32_t ah[2][4];
                    #pragma unroll
                    for (int mb = 0; mb < 2; mb++) {
                        uint32_t c = 2 * kk + achalf;
                        uint32_t aoff = arowb[mb] + ((c ^ arxor[mb]) << 4);
                        ldsm4(base + aoff, ah[mb][0], ah[mb][1], ah[mb][2], ah[mb][3]);
                    }
                    const uint32_t kb = (uint32_t)(kc * 256 + kk * 32);
                    uint32_t bh0, bh1, bh2, bh3;
                    ldsm4(sb + P_B_HI + boff + kb, bh0, bh1, bh2, bh3);
                    #pragma unroll
                    for (int mb = 0; mb < 2; mb++) {
                        mma16816(acc[mb][0], ah[mb], bh0, bh1);
                        mma16816(acc[mb][1], ah[mb], bh2, bh3);
                    }
                }
            }
            __syncthreads();   // protect A-stage region before pre-dump reuse
        }

        // dump preactivations to smem (A stage region is free now)
        #pragma unroll
        for (int mb = 0; mb < 2; mb++) {
            #pragma unroll
            for (int nb = 0; nb < 2; nb++) {
                int row = wm * 32 + mb * 16 + (l >> 2);
                int col = wn * 16 + nb * 8 + (l & 3) * 2;
                *(float2*)(pre + row * PRE_S + col) = make_float2(acc[mb][nb][0], acc[mb][nb][1]);
                *(float2*)(pre + (row + 8) * PRE_S + col) = make_float2(acc[mb][nb][2], acc[mb][nb][3]);
            }
        }
        __syncthreads();

        const int wbuf = (t + 1) & 1;
        #pragma unroll
        for (int i = 0; i < 4; i++) {
            const int m = cm[i], ul = cul[i];
            float4 pa = *(const float4*)(pre + m * PRE_S + ul * 4);
            float pf = pa.x + gx[i].x, pi = pa.y + gx[i].y;
            float pc = pa.z + gx[i].z, po = pa.w + gx[i].w;
            float fg = sigmoidf_(pf);
            float ig = sigmoidf_(pi);
            float ct = tanh_fast(pc);
            float og = sigmoidf_(po);
            float cn = fg * creg[i] + ig * ct;
            float hn = og * tanh_fast(cn);
            creg[i] = cn;
            const int u = u0 + ul;
            const int cu = m * HDIM + u;
            out[((size_t)t * BATCH + m) * HDIM + u] = hn;
            g_h[wbuf][cu] = __float2half(hn);
            if (t == T_STEPS - 1 && tail_mode > 0) {
                size_t TBH = (size_t)T_STEPS * BATCH * HDIM;
                out[TBH + cu] = hn;
                if (tail_mode > 1) out[TBH + (size_t)BATCH * HDIM + cu] = cn;
            }
        }

        // ---- grid barrier (atomic counter + single-thread acquire poll) ----
        __syncthreads();
        if (t < T_STEPS - 1) {
            if (tid == 0) {
                __threadfence();
                atomicAdd(&g_bar, 1u);
                const unsigned target = (unsigned)NCTA * (unsigned)(t + 1);
                unsigned v;
                do {
                    asm volatile("ld.global.acquire.gpu.u32 %0, [%1];"
                                 : "=r"(v) : "l"(&g_bar));
                } while (v < target);
            }
            __syncthreads();
        }
    }
}

// ---------------- launch ------------------------------------------------------
extern "C" void kernel_launch(void* const* d_in, const int* in_sizes, int n_in,
                              void* d_out, int out_size)
{
    const float* X   = (const float*)d_in[0];
    const float* Wxf = (const float*)d_in[1];
    const float* Whf = (const float*)d_in[2];
    const float* bf  = (const float*)d_in[3];
    const float* Wxi = (const float*)d_in[4];
    const float* Whi = (const float*)d_in[5];
    const float* bi  = (const float*)d_in[6];
    const float* Wxc = (const float*)d_in[7];
    const float* Whc = (const float*)d_in[8];
    const float* bc  = (const float*)d_in[9];
    const float* Wxo = (const float*)d_in[10];
    const float* Who = (const float*)d_in[11];
    const float* bo  = (const float*)d_in[12];
    float* out = (float*)d_out;

    __half *wxh, *whh;
    cudaGetSymbolAddress((void**)&wxh, g_WxTh);
    cudaGetSymbolAddress((void**)&whh, g_WhTh);

    cudaFuncSetAttribute(gemm1_kernel, cudaFuncAttributeMaxDynamicSharedMemorySize, G1_SMEM);
    cudaFuncSetAttribute(lstm_persistent_kernel, cudaFuncAttributeMaxDynamicSharedMemorySize, P_SMEM);

    cvtx_kernel<<<(TB * KDIM) / 1024, 256>>>(X);
    cvtw_kernel<<<dim3(32, 32, 4), 256>>>(Wxf, Wxi, Wxc, Wxo, wxh);
    cvtw_kernel<<<dim3(32, 32, 4), 256>>>(Whf, Whi, Whc, Who, whh);
    bias_kernel<<<4, 256>>>(bf, bi, bc, bo);  // also zeroes g_bar

    gemm1_kernel<<<dim3(NG / 128, TB / 128), 256, G1_SMEM>>>();

    long long TBH  = (long long)T_STEPS * BATCH * HDIM;
    long long tail = (long long)out_size - TBH;
    int tail_mode = (tail >= 2LL * BATCH * HDIM) ? 2 : (tail >= (long long)BATCH * HDIM) ? 1 : 0;

    lstm_persistent_kernel<<<NCTA, 256, P_SMEM>>>(out, tail_mode);
}